// round 1
// baseline (speedup 1.0000x reference)
#include <cuda_runtime.h>
#include <math.h>
#include <stdint.h>

#define BT   8192     // B*T rows
#define TT   4096     // T per batch
#define DIM  1024
#define HEADS 16
#define HS   64

// ---------------- scratch (device globals; no allocs allowed) ----------------
__device__ float g_x  [BT * DIM];        // LN1 output (also residual)
__device__ float g_q  [BT * DIM];
__device__ float g_k  [BT * DIM];
__device__ float g_v  [BT * DIM];
__device__ float g_cat[BT * 2 * DIM];    // [out_f | out_r]
__device__ float g_fb [BT * DIM];        // Wfb output (pre-LN2)
__device__ float g_y  [BT * DIM];        // LN2 output

// ---------------- helpers ----------------
__device__ __forceinline__ float block_sum_256(float v, float* sh) {
    #pragma unroll
    for (int o = 16; o; o >>= 1) v += __shfl_xor_sync(0xffffffffu, v, o);
    int w = threadIdx.x >> 5;
    if ((threadIdx.x & 31) == 0) sh[w] = v;
    __syncthreads();
    if (threadIdx.x < 8) {
        float t = sh[threadIdx.x];
        #pragma unroll
        for (int o = 4; o; o >>= 1) t += __shfl_xor_sync(0xffu, t, o);
        if (threadIdx.x == 0) sh[0] = t;
    }
    __syncthreads();
    float r = sh[0];
    __syncthreads();   // protect sh for reuse
    return r;
}

__device__ __forceinline__ float gelu_exact(float x) {
    return 0.5f * x * (1.0f + erff(x * 0.7071067811865475f));
}

// ---------------- LayerNorm (optionally fused residual add) ----------------
__global__ void ln_kernel(const float* __restrict__ in, const float* __restrict__ res,
                          const float* __restrict__ g, const float* __restrict__ b,
                          float* __restrict__ out) {
    __shared__ float sh[8];
    int row = blockIdx.x;
    const float4* pin = (const float4*)(in + (size_t)row * DIM);
    float4 v = pin[threadIdx.x];
    if (res) {
        const float4* pr = (const float4*)(res + (size_t)row * DIM);
        float4 r = pr[threadIdx.x];
        v.x += r.x; v.y += r.y; v.z += r.z; v.w += r.w;
    }
    float s = v.x + v.y + v.z + v.w;
    s = block_sum_256(s, sh);
    float mean = s * (1.0f / DIM);
    float dx = v.x - mean, dy = v.y - mean, dz = v.z - mean, dw = v.w - mean;
    float sq = dx * dx + dy * dy + dz * dz + dw * dw;
    sq = block_sum_256(sq, sh);
    float var = sq * (1.0f / DIM);
    float scale = 1.0f / sqrtf(var + 1e-6f);
    float4 gv = ((const float4*)g)[threadIdx.x];
    float4 bv = ((const float4*)b)[threadIdx.x];
    float4 o;
    o.x = dx * scale * gv.x + bv.x;
    o.y = dy * scale * gv.y + bv.y;
    o.z = dz * scale * gv.z + bv.z;
    o.w = dw * scale * gv.w + bv.w;
    ((float4*)(out + (size_t)row * DIM))[threadIdx.x] = o;
}

// ---------------- SGEMM: C[M,N] = A[M,K] @ B[K,N] + bias (+gelu) ----------------
// 128x128 tile, BK=8, 256 threads, 8x8 per thread (split 4+4 mapping).
template<bool GELU>
__global__ void __launch_bounds__(256, 2)
sgemm_bias(const float* __restrict__ A, const float* __restrict__ B,
           const float* __restrict__ bias, float* __restrict__ C,
           int M, int N, int K) {
    __shared__ float As[8][128];
    __shared__ float Bs[8][128];
    int tid = threadIdx.x;
    int tx = tid & 15, ty = tid >> 4;
    int m0 = blockIdx.y * 128, n0 = blockIdx.x * 128;

    int aRow = tid >> 1;
    int aCol = (tid & 1) * 4;
    int bRow = tid >> 5;
    int bCol = (tid & 31) * 4;

    const float* Aptr = A + (size_t)(m0 + aRow) * K + aCol;
    const float* Bptr = B + (size_t)bRow * N + n0 + bCol;

    float acc[8][8];
    #pragma unroll
    for (int i = 0; i < 8; i++)
        #pragma unroll
        for (int j = 0; j < 8; j++) acc[i][j] = 0.0f;

    for (int k0 = 0; k0 < K; k0 += 8) {
        float4 av = *(const float4*)(Aptr + k0);
        float4 bv = *(const float4*)(Bptr + (size_t)k0 * N);
        As[aCol + 0][aRow] = av.x;
        As[aCol + 1][aRow] = av.y;
        As[aCol + 2][aRow] = av.z;
        As[aCol + 3][aRow] = av.w;
        *(float4*)&Bs[bRow][bCol] = bv;
        __syncthreads();
        #pragma unroll
        for (int k = 0; k < 8; k++) {
            float4 a0 = *(const float4*)&As[k][ty * 4];
            float4 a1 = *(const float4*)&As[k][ty * 4 + 64];
            float4 b0 = *(const float4*)&Bs[k][tx * 4];
            float4 b1 = *(const float4*)&Bs[k][tx * 4 + 64];
            float ar[8] = {a0.x, a0.y, a0.z, a0.w, a1.x, a1.y, a1.z, a1.w};
            float br[8] = {b0.x, b0.y, b0.z, b0.w, b1.x, b1.y, b1.z, b1.w};
            #pragma unroll
            for (int i = 0; i < 8; i++)
                #pragma unroll
                for (int j = 0; j < 8; j++)
                    acc[i][j] += ar[i] * br[j];
        }
        __syncthreads();
    }

    #pragma unroll
    for (int i = 0; i < 8; i++) {
        int row = m0 + ty * 4 + (i & 3) + ((i >= 4) ? 64 : 0);
        #pragma unroll
        for (int jc = 0; jc < 2; jc++) {
            int col = n0 + tx * 4 + jc * 64;
            float4 bb = *(const float4*)(bias + col);
            float4 o;
            o.x = acc[i][jc * 4 + 0] + bb.x;
            o.y = acc[i][jc * 4 + 1] + bb.y;
            o.z = acc[i][jc * 4 + 2] + bb.z;
            o.w = acc[i][jc * 4 + 3] + bb.w;
            if (GELU) {
                o.x = gelu_exact(o.x); o.y = gelu_exact(o.y);
                o.z = gelu_exact(o.z); o.w = gelu_exact(o.w);
            }
            *(float4*)(C + (size_t)row * N + col) = o;
        }
    }
}

// ---------------- local windowed attention ----------------
// One warp per (b, t, head, dir). Window i (fwd) = x[t - i], (rev) = x[t + i].
// Query = window 1; keys/values = windows 0..2; OOB windows are zero vectors
// that still participate in softmax (score 0) — matches masked-gather reference.
__global__ void attn_kernel(const float* __restrict__ q, const float* __restrict__ k,
                            const float* __restrict__ v, float* __restrict__ cat) {
    int warp = (blockIdx.x * blockDim.x + threadIdx.x) >> 5;
    int lane = threadIdx.x & 31;
    int dir = warp & 1;
    int h   = (warp >> 1) & 15;
    int tg  = warp >> 5;            // 0..BT-1
    int b   = tg >> 12;
    int t   = tg & (TT - 1);
    int step = dir ? 1 : -1;
    int base = b << 12;             // b * TT
    int off  = h * HS + lane * 2;

    int tq = t + step;
    float2 qv = make_float2(0.0f, 0.0f);
    if (tq >= 0 && tq < TT)
        qv = *(const float2*)(q + (size_t)(base + tq) * DIM + off);

    float s[3];
    float2 vv[3];
    #pragma unroll
    for (int j = 0; j < 3; j++) {
        int tk = t + step * j;
        float2 kv = make_float2(0.0f, 0.0f);
        float2 vj = make_float2(0.0f, 0.0f);
        if (tk >= 0 && tk < TT) {
            kv = *(const float2*)(k + (size_t)(base + tk) * DIM + off);
            vj = *(const float2*)(v + (size_t)(base + tk) * DIM + off);
        }
        float p = qv.x * kv.x + qv.y * kv.y;
        #pragma unroll
        for (int o = 16; o; o >>= 1) p += __shfl_xor_sync(0xffffffffu, p, o);
        s[j] = p * 0.125f;          // 1/sqrt(HS=64)
        vv[j] = vj;
    }
    float m  = fmaxf(s[0], fmaxf(s[1], s[2]));
    float e0 = expf(s[0] - m), e1 = expf(s[1] - m), e2 = expf(s[2] - m);
    float inv = 1.0f / (e0 + e1 + e2);
    float2 o;
    o.x = (e0 * vv[0].x + e1 * vv[1].x + e2 * vv[2].x) * inv;
    o.y = (e0 * vv[0].y + e1 * vv[1].y + e2 * vv[2].y) * inv;
    *(float2*)(cat + (size_t)(base + t) * (2 * DIM) + dir * DIM + off) = o;
}

// ---------------- launch ----------------
extern "C" void kernel_launch(void* const* d_in, const int* in_sizes, int n_in,
                              void* d_out, int out_size) {
    const float* inp = (const float*)d_in[0];
    const float* Wq  = (const float*)d_in[1];
    const float* bq  = (const float*)d_in[2];
    const float* Wk  = (const float*)d_in[3];
    const float* bk  = (const float*)d_in[4];
    const float* Wv  = (const float*)d_in[5];
    const float* bv  = (const float*)d_in[6];
    const float* Wfb = (const float*)d_in[7];
    const float* bfb = (const float*)d_in[8];
    const float* Wo  = (const float*)d_in[9];
    const float* bo  = (const float*)d_in[10];
    const float* g1  = (const float*)d_in[11];
    const float* b1  = (const float*)d_in[12];
    const float* g2  = (const float*)d_in[13];
    const float* b2  = (const float*)d_in[14];
    float* out = (float*)d_out;

    float *xp, *qp, *kp, *vp, *catp, *fbp, *yp;
    cudaGetSymbolAddress((void**)&xp,  g_x);
    cudaGetSymbolAddress((void**)&qp,  g_q);
    cudaGetSymbolAddress((void**)&kp,  g_k);
    cudaGetSymbolAddress((void**)&vp,  g_v);
    cudaGetSymbolAddress((void**)&catp, g_cat);
    cudaGetSymbolAddress((void**)&fbp, g_fb);
    cudaGetSymbolAddress((void**)&yp,  g_y);

    // LN1
    ln_kernel<<<BT, 256>>>(inp, nullptr, g1, b1, xp);

    // q, k, v projections
    dim3 gq(DIM / 128, BT / 128);
    sgemm_bias<false><<<gq, 256>>>(xp, Wq, bq, qp, BT, DIM, DIM);
    sgemm_bias<false><<<gq, 256>>>(xp, Wk, bk, kp, BT, DIM, DIM);
    sgemm_bias<false><<<gq, 256>>>(xp, Wv, bv, vp, BT, DIM, DIM);

    // local attention -> cat buffer  (BT * HEADS * 2 warps, 8 warps/block)
    attn_kernel<<<(BT * HEADS * 2) / 8, 256>>>(qp, kp, vp, catp);

    // feedback projection (K = 2048)
    sgemm_bias<false><<<gq, 256>>>(catp, Wfb, bfb, fbp, BT, DIM, 2 * DIM);

    // residual + LN2
    ln_kernel<<<BT, 256>>>(fbp, xp, g2, b2, yp);

    // output projection + GELU
    sgemm_bias<true><<<gq, 256>>>(yp, Wo, bo, out, BT, DIM, DIM);
}

// round 4
// speedup vs baseline: 3.0404x; 3.0404x over previous
#include <cuda_runtime.h>
#include <math.h>
#include <stdint.h>

#define BT   8192
#define TT   4096
#define DIM  1024
#define HS   64

// ---------------- scratch (device globals) ----------------
__device__ float g_x  [BT * DIM];        // LN1 out fp32 (residual)
__device__ float g_xr [BT * DIM];        // LN1 out tf32-rounded
__device__ float g_q  [BT * DIM];
__device__ float g_k  [BT * DIM];
__device__ float g_v  [BT * DIM];
__device__ float g_cat[BT * 2 * DIM];    // tf32-rounded
__device__ float g_fb [BT * DIM];
__device__ float g_y  [BT * DIM];        // LN2 out tf32-rounded
__device__ float g_wq [DIM * DIM];       // tf32-rounded weights (same [K,N] layout)
__device__ float g_wk [DIM * DIM];
__device__ float g_wv [DIM * DIM];
__device__ float g_wo [DIM * DIM];
__device__ float g_wfb[2 * DIM * DIM];

// ---------------- helpers ----------------
__device__ __forceinline__ uint32_t smem_u32(const void* p) {
    uint32_t a;
    asm("{ .reg .u64 t; cvta.to.shared.u64 t, %1; cvt.u32.u64 %0, t; }" : "=r"(a) : "l"(p));
    return a;
}
__device__ __forceinline__ float tf32r(float x) {
    uint32_t y;
    asm("cvt.rna.tf32.f32 %0, %1;" : "=r"(y) : "f"(x));
    return __uint_as_float(y);
}
__device__ __forceinline__ float gelu_exact(float x) {
    return 0.5f * x * (1.0f + erff(x * 0.7071067811865475f));
}
__device__ __forceinline__ float block_sum_256(float v, float* sh) {
    #pragma unroll
    for (int o = 16; o; o >>= 1) v += __shfl_xor_sync(0xffffffffu, v, o);
    int w = threadIdx.x >> 5;
    if ((threadIdx.x & 31) == 0) sh[w] = v;
    __syncthreads();
    if (threadIdx.x < 8) {
        float t = sh[threadIdx.x];
        #pragma unroll
        for (int o = 4; o; o >>= 1) t += __shfl_xor_sync(0xffu, t, o);
        if (threadIdx.x == 0) sh[0] = t;
    }
    __syncthreads();
    float r = sh[0];
    __syncthreads();
    return r;
}

__device__ __forceinline__ void mma_tf32(float* c, const uint32_t* a, const uint32_t* b) {
    asm volatile(
        "mma.sync.aligned.m16n8k8.row.col.f32.tf32.tf32.f32 "
        "{%0,%1,%2,%3}, {%4,%5,%6,%7}, {%8,%9}, {%0,%1,%2,%3};"
        : "+f"(c[0]), "+f"(c[1]), "+f"(c[2]), "+f"(c[3])
        : "r"(a[0]), "r"(a[1]), "r"(a[2]), "r"(a[3]), "r"(b[0]), "r"(b[1]));
}

#define CP16(dst, src) \
    asm volatile("cp.async.cg.shared.global [%0], [%1], 16;" :: "r"(dst), "l"(src))
#define CP_COMMIT() asm volatile("cp.async.commit_group;" ::: "memory")
#define CP_WAIT1()  asm volatile("cp.async.wait_group 1;" ::: "memory")
#define CP_WAIT0()  asm volatile("cp.async.wait_group 0;" ::: "memory")

// ---------------- LayerNorm (dual output fp32 / tf32) ----------------
__global__ void ln_kernel(const float* __restrict__ in, const float* __restrict__ res,
                          const float* __restrict__ g, const float* __restrict__ b,
                          float* __restrict__ out32, float* __restrict__ outr) {
    __shared__ float sh[8];
    int row = blockIdx.x;
    float4 v = ((const float4*)(in + (size_t)row * DIM))[threadIdx.x];
    if (res) {
        float4 r = ((const float4*)(res + (size_t)row * DIM))[threadIdx.x];
        v.x += r.x; v.y += r.y; v.z += r.z; v.w += r.w;
    }
    float s = block_sum_256(v.x + v.y + v.z + v.w, sh);
    float mean = s * (1.0f / DIM);
    float dx = v.x - mean, dy = v.y - mean, dz = v.z - mean, dw = v.w - mean;
    float sq = block_sum_256(dx*dx + dy*dy + dz*dz + dw*dw, sh);
    float scale = rsqrtf(sq * (1.0f / DIM) + 1e-6f);
    float4 gv = ((const float4*)g)[threadIdx.x];
    float4 bv = ((const float4*)b)[threadIdx.x];
    float4 o;
    o.x = dx * scale * gv.x + bv.x;
    o.y = dy * scale * gv.y + bv.y;
    o.z = dz * scale * gv.z + bv.z;
    o.w = dw * scale * gv.w + bv.w;
    if (out32) ((float4*)(out32 + (size_t)row * DIM))[threadIdx.x] = o;
    if (outr) {
        float4 t;
        t.x = tf32r(o.x); t.y = tf32r(o.y); t.z = tf32r(o.z); t.w = tf32r(o.w);
        ((float4*)(outr + (size_t)row * DIM))[threadIdx.x] = t;
    }
}

// ---------------- tf32 rounding copy for weights ----------------
__global__ void round_copy(const float* __restrict__ src, float* __restrict__ dst, int n4) {
    int i = blockIdx.x * blockDim.x + threadIdx.x;
    if (i < n4) {
        float4 v = ((const float4*)src)[i];
        float4 t;
        t.x = tf32r(v.x); t.y = tf32r(v.y); t.z = tf32r(v.z); t.w = tf32r(v.w);
        ((float4*)dst)[i] = t;
    }
}

// ---------------- tensor-core GEMM via mma.sync (tf32) ----------------
// C[M,1024] = A[M,K] @ B[K,1024] + bias (+gelu). A,B pre-rounded to tf32.
// 128x128x32 tiles, 3-stage cp.async ring, 8 warps (2x4), 64x32 warp tiles.
#define AS_STRIDE 36
#define BS_STRIDE 136
#define AS_SZ (128 * AS_STRIDE)   // floats per stage
#define BS_SZ (32 * BS_STRIDE)
#define GSMEM_BYTES ((3 * AS_SZ + 3 * BS_SZ) * 4)   // 107520

template<bool GELU>
__global__ void __launch_bounds__(256, 2)
gemm_mma(const float* __restrict__ A, const float* __restrict__ B,
         const float* __restrict__ bias, float* __restrict__ C, int K) {
    extern __shared__ __align__(16) float smem[];
    float* As = smem;               // 3 stages
    float* Bs = smem + 3 * AS_SZ;

    int tid = threadIdx.x;
    int wid = tid >> 5, lane = tid & 31;
    int wm = (wid >> 2) * 64;       // warp m offset (0/64)
    int wn = (wid & 3) * 32;        // warp n offset
    int g = lane >> 2, t4 = lane & 3;
    int m0 = blockIdx.y << 7, n0 = blockIdx.x << 7;

    float acc[4][4][4];
    #pragma unroll
    for (int i = 0; i < 4; i++)
        #pragma unroll
        for (int j = 0; j < 4; j++)
            #pragma unroll
            for (int q = 0; q < 4; q++) acc[i][j][q] = 0.0f;

    auto cp_stage = [&](int s, int c) {
        int k0 = c << 5;
        #pragma unroll
        for (int j = 0; j < 4; j++) {
            int idx = tid + (j << 8);
            int ar = idx >> 3, ac = (idx & 7) << 2;
            uint32_t ad = smem_u32(&As[s * AS_SZ + ar * AS_STRIDE + ac]);
            CP16(ad, A + (size_t)(m0 + ar) * K + k0 + ac);
            int br = idx >> 5, bc = (idx & 31) << 2;
            uint32_t bd = smem_u32(&Bs[s * BS_SZ + br * BS_STRIDE + bc]);
            CP16(bd, B + (size_t)(k0 + br) * DIM + n0 + bc);
        }
        CP_COMMIT();
    };

    int NC = K >> 5;
    cp_stage(0, 0);
    cp_stage(1, 1);

    for (int c = 0; c < NC; c++) {
        if (c + 1 < NC) CP_WAIT1(); else CP_WAIT0();
        __syncthreads();
        if (c + 2 < NC) cp_stage((c + 2) % 3, c + 2);

        int s = c % 3;
        const float* as = As + s * AS_SZ + wm * AS_STRIDE;
        const float* bs = Bs + s * BS_SZ + wn;
        #pragma unroll
        for (int kk = 0; kk < 4; kk++) {
            int k8 = kk << 3;
            uint32_t af[4][4], bf[4][2];
            #pragma unroll
            for (int mt = 0; mt < 4; mt++) {
                const float* p = as + (mt * 16 + g) * AS_STRIDE + k8;
                af[mt][0] = __float_as_uint(p[t4]);
                af[mt][1] = __float_as_uint(p[8 * AS_STRIDE + t4]);
                af[mt][2] = __float_as_uint(p[t4 + 4]);
                af[mt][3] = __float_as_uint(p[8 * AS_STRIDE + t4 + 4]);
            }
            #pragma unroll
            for (int nt = 0; nt < 4; nt++) {
                const float* p = bs + (k8 + t4) * BS_STRIDE + nt * 8 + g;
                bf[nt][0] = __float_as_uint(p[0]);
                bf[nt][1] = __float_as_uint(p[4 * BS_STRIDE]);
            }
            #pragma unroll
            for (int mt = 0; mt < 4; mt++)
                #pragma unroll
                for (int nt = 0; nt < 4; nt++)
                    mma_tf32(acc[mt][nt], af[mt], bf[nt]);
        }
        __syncthreads();
    }

    // epilogue: c0/c1 at (row, col..col+1), c2/c3 at (row+8, ...)
    #pragma unroll
    for (int mt = 0; mt < 4; mt++) {
        int row = m0 + wm + mt * 16 + g;
        #pragma unroll
        for (int nt = 0; nt < 4; nt++) {
            int col = n0 + wn + nt * 8 + 2 * t4;
            float b0 = bias[col], b1 = bias[col + 1];
            float2 o0, o1;
            o0.x = acc[mt][nt][0] + b0; o0.y = acc[mt][nt][1] + b1;
            o1.x = acc[mt][nt][2] + b0; o1.y = acc[mt][nt][3] + b1;
            if (GELU) {
                o0.x = gelu_exact(o0.x); o0.y = gelu_exact(o0.y);
                o1.x = gelu_exact(o1.x); o1.y = gelu_exact(o1.y);
            }
            *(float2*)(C + (size_t)row * DIM + col) = o0;
            *(float2*)(C + (size_t)(row + 8) * DIM + col) = o1;
        }
    }
}

// ---------------- local windowed attention (outputs tf32-rounded) ----------------
__global__ void attn_kernel(const float* __restrict__ q, const float* __restrict__ k,
                            const float* __restrict__ v, float* __restrict__ cat) {
    int warp = (blockIdx.x * blockDim.x + threadIdx.x) >> 5;
    int lane = threadIdx.x & 31;
    int dir = warp & 1;
    int h   = (warp >> 1) & 15;
    int tg  = warp >> 5;
    int b   = tg >> 12;
    int t   = tg & (TT - 1);
    int step = dir ? 1 : -1;
    int base = b << 12;
    int off  = h * HS + lane * 2;

    int tq = t + step;
    float2 qv = make_float2(0.0f, 0.0f);
    if (tq >= 0 && tq < TT)
        qv = *(const float2*)(q + (size_t)(base + tq) * DIM + off);

    float s[3];
    float2 vv[3];
    #pragma unroll
    for (int j = 0; j < 3; j++) {
        int tk = t + step * j;
        float2 kv = make_float2(0.0f, 0.0f);
        float2 vj = make_float2(0.0f, 0.0f);
        if (tk >= 0 && tk < TT) {
            kv = *(const float2*)(k + (size_t)(base + tk) * DIM + off);
            vj = *(const float2*)(v + (size_t)(base + tk) * DIM + off);
        }
        float p = qv.x * kv.x + qv.y * kv.y;
        #pragma unroll
        for (int o = 16; o; o >>= 1) p += __shfl_xor_sync(0xffffffffu, p, o);
        s[j] = p * 0.125f;
        vv[j] = vj;
    }
    float m  = fmaxf(s[0], fmaxf(s[1], s[2]));
    float e0 = expf(s[0] - m), e1 = expf(s[1] - m), e2 = expf(s[2] - m);
    float inv = 1.0f / (e0 + e1 + e2);
    float2 o;
    o.x = tf32r((e0 * vv[0].x + e1 * vv[1].x + e2 * vv[2].x) * inv);
    o.y = tf32r((e0 * vv[0].y + e1 * vv[1].y + e2 * vv[2].y) * inv);
    *(float2*)(cat + (size_t)(base + t) * (2 * DIM) + dir * DIM + off) = o;
}

// ---------------- launch ----------------
extern "C" void kernel_launch(void* const* d_in, const int* in_sizes, int n_in,
                              void* d_out, int out_size) {
    const float* inp = (const float*)d_in[0];
    const float* Wq  = (const float*)d_in[1];
    const float* bq  = (const float*)d_in[2];
    const float* Wk  = (const float*)d_in[3];
    const float* bk  = (const float*)d_in[4];
    const float* Wv  = (const float*)d_in[5];
    const float* bv  = (const float*)d_in[6];
    const float* Wfb = (const float*)d_in[7];
    const float* bfb = (const float*)d_in[8];
    const float* Wo  = (const float*)d_in[9];
    const float* bo  = (const float*)d_in[10];
    const float* g1  = (const float*)d_in[11];
    const float* b1  = (const float*)d_in[12];
    const float* g2  = (const float*)d_in[13];
    const float* b2  = (const float*)d_in[14];
    float* out = (float*)d_out;

    float *xp, *xrp, *qp, *kp, *vp, *catp, *fbp, *yp;
    float *wq, *wk, *wv, *wo, *wfb;
    cudaGetSymbolAddress((void**)&xp,   g_x);
    cudaGetSymbolAddress((void**)&xrp,  g_xr);
    cudaGetSymbolAddress((void**)&qp,   g_q);
    cudaGetSymbolAddress((void**)&kp,   g_k);
    cudaGetSymbolAddress((void**)&vp,   g_v);
    cudaGetSymbolAddress((void**)&catp, g_cat);
    cudaGetSymbolAddress((void**)&fbp,  g_fb);
    cudaGetSymbolAddress((void**)&yp,   g_y);
    cudaGetSymbolAddress((void**)&wq,   g_wq);
    cudaGetSymbolAddress((void**)&wk,   g_wk);
    cudaGetSymbolAddress((void**)&wv,   g_wv);
    cudaGetSymbolAddress((void**)&wo,   g_wo);
    cudaGetSymbolAddress((void**)&wfb,  g_wfb);

    cudaFuncSetAttribute(gemm_mma<false>, cudaFuncAttributeMaxDynamicSharedMemorySize, GSMEM_BYTES);
    cudaFuncSetAttribute(gemm_mma<true>,  cudaFuncAttributeMaxDynamicSharedMemorySize, GSMEM_BYTES);

    int n4 = DIM * DIM / 4;
    round_copy<<<(n4 + 255) / 256, 256>>>(Wq, wq, n4);
    round_copy<<<(n4 + 255) / 256, 256>>>(Wk, wk, n4);
    round_copy<<<(n4 + 255) / 256, 256>>>(Wv, wv, n4);
    round_copy<<<(n4 + 255) / 256, 256>>>(Wo, wo, n4);
    round_copy<<<(2 * n4 + 255) / 256, 256>>>(Wfb, wfb, 2 * n4);

    ln_kernel<<<BT, 256>>>(inp, nullptr, g1, b1, xp, xrp);

    dim3 gg(DIM / 128, BT / 128);
    gemm_mma<false><<<gg, 256, GSMEM_BYTES>>>(xrp, wq, bq, qp, DIM);
    gemm_mma<false><<<gg, 256, GSMEM_BYTES>>>(xrp, wk, bk, kp, DIM);
    gemm_mma<false><<<gg, 256, GSMEM_BYTES>>>(xrp, wv, bv, vp, DIM);

    attn_kernel<<<(BT * 16 * 2) / 8, 256>>>(qp, kp, vp, catp);

    gemm_mma<false><<<gg, 256, GSMEM_BYTES>>>(catp, wfb, bfb, fbp, 2 * DIM);

    ln_kernel<<<BT, 256>>>(fbp, xp, g2, b2, nullptr, yp);

    gemm_mma<true><<<gg, 256, GSMEM_BYTES>>>(yp, wo, bo, out, DIM);
}

// round 5
// speedup vs baseline: 4.6526x; 1.5303x over previous
#include <cuda_runtime.h>
#include <cuda_fp16.h>
#include <math.h>
#include <stdint.h>

#define BT   8192
#define TT   4096
#define DIM  1024

// ---------------- scratch (device globals) ----------------
__device__ float  g_x  [BT * DIM];          // LN1 out fp32 (residual)
__device__ __half g_xh [BT * DIM];          // LN1 out fp16
__device__ __half g_qkv[BT * 3 * DIM];      // fused q|k|v
__device__ __half g_cat[BT * 2 * DIM];      // attn out (fwd|rev)
__device__ float  g_fb [BT * DIM];          // Wfb out fp32 (pre-LN2)
__device__ __half g_yh [BT * DIM];          // LN2 out fp16
__device__ __half g_wqkvT[3 * DIM * DIM];   // [3072][1024] = W^T fp16
__device__ __half g_wfbT [DIM * 2 * DIM];   // [1024][2048]
__device__ __half g_woT  [DIM * DIM];       // [1024][1024]
__device__ float  g_bqkv [3 * DIM];

// ---------------- helpers ----------------
__device__ __forceinline__ uint32_t smem_u32(const void* p) {
    uint32_t a;
    asm("{ .reg .u64 t; cvta.to.shared.u64 t, %1; cvt.u32.u64 %0, t; }" : "=r"(a) : "l"(p));
    return a;
}
__device__ __forceinline__ float gelu_exact(float x) {
    return 0.5f * x * (1.0f + erff(x * 0.7071067811865475f));
}
__device__ __forceinline__ float block_sum_256(float v, float* sh) {
    #pragma unroll
    for (int o = 16; o; o >>= 1) v += __shfl_xor_sync(0xffffffffu, v, o);
    int w = threadIdx.x >> 5;
    if ((threadIdx.x & 31) == 0) sh[w] = v;
    __syncthreads();
    if (threadIdx.x < 8) {
        float t = sh[threadIdx.x];
        #pragma unroll
        for (int o = 4; o; o >>= 1) t += __shfl_xor_sync(0xffu, t, o);
        if (threadIdx.x == 0) sh[0] = t;
    }
    __syncthreads();
    float r = sh[0];
    __syncthreads();
    return r;
}

__device__ __forceinline__ void mma_fp16(float* c, const uint32_t* a, const uint32_t* b) {
    asm volatile(
        "mma.sync.aligned.m16n8k16.row.col.f32.f16.f16.f32 "
        "{%0,%1,%2,%3}, {%4,%5,%6,%7}, {%8,%9}, {%0,%1,%2,%3};"
        : "+f"(c[0]), "+f"(c[1]), "+f"(c[2]), "+f"(c[3])
        : "r"(a[0]), "r"(a[1]), "r"(a[2]), "r"(a[3]), "r"(b[0]), "r"(b[1]));
}

#define CP16(dst, src) \
    asm volatile("cp.async.cg.shared.global [%0], [%1], 16;" :: "r"(dst), "l"(src))
#define CP_COMMIT() asm volatile("cp.async.commit_group;" ::: "memory")
#define CP_WAIT2()  asm volatile("cp.async.wait_group 2;" ::: "memory")

// ---------------- LayerNorm: fp32 in (+res) -> optional fp32 out + fp16 out ----------------
__global__ void ln_kernel(const float* __restrict__ in, const float* __restrict__ res,
                          const float* __restrict__ g, const float* __restrict__ b,
                          float* __restrict__ out32, __half* __restrict__ outh) {
    __shared__ float sh[8];
    int row = blockIdx.x;
    float4 v = ((const float4*)(in + (size_t)row * DIM))[threadIdx.x];
    if (res) {
        float4 r = ((const float4*)(res + (size_t)row * DIM))[threadIdx.x];
        v.x += r.x; v.y += r.y; v.z += r.z; v.w += r.w;
    }
    float s = block_sum_256(v.x + v.y + v.z + v.w, sh);
    float mean = s * (1.0f / DIM);
    float dx = v.x - mean, dy = v.y - mean, dz = v.z - mean, dw = v.w - mean;
    float sq = block_sum_256(dx*dx + dy*dy + dz*dz + dw*dw, sh);
    float scale = rsqrtf(sq * (1.0f / DIM) + 1e-6f);
    float4 gv = ((const float4*)g)[threadIdx.x];
    float4 bv = ((const float4*)b)[threadIdx.x];
    float4 o;
    o.x = dx * scale * gv.x + bv.x;
    o.y = dy * scale * gv.y + bv.y;
    o.z = dz * scale * gv.z + bv.z;
    o.w = dw * scale * gv.w + bv.w;
    if (out32) ((float4*)(out32 + (size_t)row * DIM))[threadIdx.x] = o;
    if (outh) {
        __half2* ph = (__half2*)(outh + (size_t)row * DIM);
        ph[2 * threadIdx.x + 0] = __floats2half2_rn(o.x, o.y);
        ph[2 * threadIdx.x + 1] = __floats2half2_rn(o.z, o.w);
    }
}

// ---------------- weight transpose+convert: W[R,C] fp32 -> WT[C,R] fp16 ----------------
__global__ void transpose_h(const float* __restrict__ W, __half* __restrict__ WT, int R, int C) {
    __shared__ float t[32][33];
    int c0 = blockIdx.x * 32, r0 = blockIdx.y * 32;
    int x = threadIdx.x, y = threadIdx.y;
    #pragma unroll
    for (int i = 0; i < 32; i += 8)
        t[y + i][x] = W[(size_t)(r0 + y + i) * C + c0 + x];
    __syncthreads();
    #pragma unroll
    for (int i = 0; i < 32; i += 8)
        WT[(size_t)(c0 + y + i) * R + r0 + x] = __float2half_rn(t[x][y + i]);
}

__global__ void concat_bias(const float* __restrict__ a, const float* __restrict__ b,
                            const float* __restrict__ c, float* __restrict__ o) {
    int i = blockIdx.x * blockDim.x + threadIdx.x;
    if (i < DIM) o[i] = a[i];
    else if (i < 2 * DIM) o[i] = b[i - DIM];
    else if (i < 3 * DIM) o[i] = c[i - 2 * DIM];
}

// ---------------- fp16 tensor-core GEMM ----------------
// C[M,N] = A[M,K] @ BT[N,K]^T + bias (+gelu).  256x128x32 tiles, 8 warps (4x2),
// 64x64 warp tiles, 4-stage cp.async ring, one __syncthreads per chunk.
#define ASH     40                       // A smem row stride (halves)
#define ASTAGE  (256 * ASH)              // halves
#define BSTAGE  (128 * ASH)
#define GSMEM_BYTES (4 * (ASTAGE + BSTAGE) * 2)   // 122880

template<typename OUT, bool GELU>
__global__ void __launch_bounds__(256, 1)
gemm_h(const __half* __restrict__ A, const __half* __restrict__ Bt,
       const float* __restrict__ bias, OUT* __restrict__ C, int N, int K) {
    extern __shared__ __align__(16) __half hsm[];
    __half* As = hsm;
    __half* Bs = hsm + 4 * ASTAGE;

    int tid = threadIdx.x;
    int wid = tid >> 5, lane = tid & 31;
    int wm = (wid >> 1) * 64;            // 4 m-warps
    int wn = (wid & 1) * 64;             // 2 n-warps
    int g = lane >> 2, t4 = lane & 3;
    int m0 = blockIdx.y << 8, n0 = blockIdx.x << 7;

    float acc[4][8][4];
    #pragma unroll
    for (int i = 0; i < 4; i++)
        #pragma unroll
        for (int j = 0; j < 8; j++)
            #pragma unroll
            for (int q = 0; q < 4; q++) acc[i][j][q] = 0.0f;

    auto cp_stage = [&](int s, int c) {
        const __half* Ab = A + (size_t)m0 * K + c * 32;
        #pragma unroll
        for (int j = 0; j < 4; j++) {
            int idx = tid + (j << 8);
            int ar = idx >> 2, ac = (idx & 3) << 3;
            CP16(smem_u32(As + s * ASTAGE + ar * ASH + ac), Ab + (size_t)ar * K + ac);
        }
        const __half* Bb = Bt + (size_t)n0 * K + c * 32;
        #pragma unroll
        for (int j = 0; j < 2; j++) {
            int idx = tid + (j << 8);
            int br = idx >> 2, bc = (idx & 3) << 3;
            CP16(smem_u32(Bs + s * BSTAGE + br * ASH + bc), Bb + (size_t)br * K + bc);
        }
        CP_COMMIT();
    };

    int NC = K >> 5;
    cp_stage(0, 0);
    cp_stage(1, 1);
    cp_stage(2, 2);

    for (int c = 0; c < NC; c++) {
        CP_WAIT2();
        __syncthreads();
        if (c + 3 < NC) cp_stage((c + 3) & 3, c + 3);
        else CP_COMMIT();                 // keep pending-group count exact

        int s = c & 3;
        const __half* as = As + s * ASTAGE + wm * ASH;
        const __half* bs = Bs + s * BSTAGE + wn * ASH;
        #pragma unroll
        for (int kk = 0; kk < 2; kk++) {
            int kb = kk * 16 + 2 * t4;
            uint32_t af[4][4], bf[8][2];
            #pragma unroll
            for (int mt = 0; mt < 4; mt++) {
                const __half* p = as + (mt * 16 + g) * ASH + kb;
                af[mt][0] = *(const uint32_t*)(p);
                af[mt][1] = *(const uint32_t*)(p + 8 * ASH);
                af[mt][2] = *(const uint32_t*)(p + 8);
                af[mt][3] = *(const uint32_t*)(p + 8 * ASH + 8);
            }
            #pragma unroll
            for (int nt = 0; nt < 8; nt++) {
                const __half* p = bs + (nt * 8 + g) * ASH + kb;
                bf[nt][0] = *(const uint32_t*)(p);
                bf[nt][1] = *(const uint32_t*)(p + 8);
            }
            #pragma unroll
            for (int mt = 0; mt < 4; mt++)
                #pragma unroll
                for (int nt = 0; nt < 8; nt++)
                    mma_fp16(acc[mt][nt], af[mt], bf[nt]);
        }
    }

    // epilogue
    #pragma unroll
    for (int mt = 0; mt < 4; mt++) {
        int row = m0 + wm + mt * 16 + g;
        #pragma unroll
        for (int nt = 0; nt < 8; nt++) {
            int col = n0 + wn + nt * 8 + 2 * t4;
            float b0 = bias[col], b1 = bias[col + 1];
            float v00 = acc[mt][nt][0] + b0, v01 = acc[mt][nt][1] + b1;
            float v10 = acc[mt][nt][2] + b0, v11 = acc[mt][nt][3] + b1;
            if (GELU) {
                v00 = gelu_exact(v00); v01 = gelu_exact(v01);
                v10 = gelu_exact(v10); v11 = gelu_exact(v11);
            }
            if (sizeof(OUT) == 2) {
                *(__half2*)((__half*)C + (size_t)row * N + col) = __floats2half2_rn(v00, v01);
                *(__half2*)((__half*)C + (size_t)(row + 8) * N + col) = __floats2half2_rn(v10, v11);
            } else {
                *(float2*)((float*)C + (size_t)row * N + col) = make_float2(v00, v01);
                *(float2*)((float*)C + (size_t)(row + 8) * N + col) = make_float2(v10, v11);
            }
        }
    }
}

// ---------------- local windowed attention over fused qkv ----------------
__global__ void attn_kernel(const __half* __restrict__ qkv, __half* __restrict__ cat) {
    int warp = (blockIdx.x * blockDim.x + threadIdx.x) >> 5;
    int lane = threadIdx.x & 31;
    int dir = warp & 1;
    int h   = (warp >> 1) & 15;
    int tg  = warp >> 5;
    int b   = tg >> 12;
    int t   = tg & (TT - 1);
    int step = dir ? 1 : -1;
    int base = b << 12;
    int off  = h * 64 + lane * 2;

    int tq = t + step;
    float2 qv = make_float2(0.0f, 0.0f);
    if (tq >= 0 && tq < TT)
        qv = __half22float2(*(const __half2*)(qkv + (size_t)(base + tq) * 3072 + off));

    float s[3];
    float2 vv[3];
    #pragma unroll
    for (int j = 0; j < 3; j++) {
        int tk = t + step * j;
        float2 kv = make_float2(0.0f, 0.0f);
        float2 vj = make_float2(0.0f, 0.0f);
        if (tk >= 0 && tk < TT) {
            const __half* rp = qkv + (size_t)(base + tk) * 3072 + off;
            kv = __half22float2(*(const __half2*)(rp + DIM));
            vj = __half22float2(*(const __half2*)(rp + 2 * DIM));
        }
        float p = qv.x * kv.x + qv.y * kv.y;
        #pragma unroll
        for (int o = 16; o; o >>= 1) p += __shfl_xor_sync(0xffffffffu, p, o);
        s[j] = p * 0.125f;
        vv[j] = vj;
    }
    float m  = fmaxf(s[0], fmaxf(s[1], s[2]));
    float e0 = expf(s[0] - m), e1 = expf(s[1] - m), e2 = expf(s[2] - m);
    float inv = 1.0f / (e0 + e1 + e2);
    float ox = (e0 * vv[0].x + e1 * vv[1].x + e2 * vv[2].x) * inv;
    float oy = (e0 * vv[0].y + e1 * vv[1].y + e2 * vv[2].y) * inv;
    *(__half2*)(cat + (size_t)(base + t) * (2 * DIM) + dir * DIM + off) = __floats2half2_rn(ox, oy);
}

// ---------------- launch ----------------
extern "C" void kernel_launch(void* const* d_in, const int* in_sizes, int n_in,
                              void* d_out, int out_size) {
    const float* inp = (const float*)d_in[0];
    const float* Wq  = (const float*)d_in[1];
    const float* bq  = (const float*)d_in[2];
    const float* Wk  = (const float*)d_in[3];
    const float* bk  = (const float*)d_in[4];
    const float* Wv  = (const float*)d_in[5];
    const float* bv  = (const float*)d_in[6];
    const float* Wfb = (const float*)d_in[7];
    const float* bfb = (const float*)d_in[8];
    const float* Wo  = (const float*)d_in[9];
    const float* bo  = (const float*)d_in[10];
    const float* g1  = (const float*)d_in[11];
    const float* b1  = (const float*)d_in[12];
    const float* g2  = (const float*)d_in[13];
    const float* b2  = (const float*)d_in[14];
    float* out = (float*)d_out;

    float *xp, *fbp, *bqkvp;
    __half *xhp, *qkvp, *catp, *yhp, *wqkvT, *wfbT, *woT;
    cudaGetSymbolAddress((void**)&xp,    g_x);
    cudaGetSymbolAddress((void**)&xhp,   g_xh);
    cudaGetSymbolAddress((void**)&qkvp,  g_qkv);
    cudaGetSymbolAddress((void**)&catp,  g_cat);
    cudaGetSymbolAddress((void**)&fbp,   g_fb);
    cudaGetSymbolAddress((void**)&yhp,   g_yh);
    cudaGetSymbolAddress((void**)&wqkvT, g_wqkvT);
    cudaGetSymbolAddress((void**)&wfbT,  g_wfbT);
    cudaGetSymbolAddress((void**)&woT,   g_woT);
    cudaGetSymbolAddress((void**)&bqkvp, g_bqkv);

    cudaFuncSetAttribute(gemm_h<__half, false>, cudaFuncAttributeMaxDynamicSharedMemorySize, GSMEM_BYTES);
    cudaFuncSetAttribute(gemm_h<float, false>,  cudaFuncAttributeMaxDynamicSharedMemorySize, GSMEM_BYTES);
    cudaFuncSetAttribute(gemm_h<float, true>,   cudaFuncAttributeMaxDynamicSharedMemorySize, GSMEM_BYTES);

    dim3 tt(32, 8);
    transpose_h<<<dim3(32, 32), tt>>>(Wq,  wqkvT,                DIM, DIM);
    transpose_h<<<dim3(32, 32), tt>>>(Wk,  wqkvT + DIM * DIM,     DIM, DIM);
    transpose_h<<<dim3(32, 32), tt>>>(Wv,  wqkvT + 2 * DIM * DIM, DIM, DIM);
    transpose_h<<<dim3(32, 64), tt>>>(Wfb, wfbT, 2 * DIM, DIM);
    transpose_h<<<dim3(32, 32), tt>>>(Wo,  woT,  DIM, DIM);
    concat_bias<<<12, 256>>>(bq, bk, bv, bqkvp);

    // LN1: fp32 residual + fp16 GEMM operand
    ln_kernel<<<BT, 256>>>(inp, nullptr, g1, b1, xp, xhp);

    // fused QKV projection: [8192,1024] @ [1024,3072]
    gemm_h<__half, false><<<dim3(3 * DIM / 128, BT / 256), 256, GSMEM_BYTES>>>(
        xhp, wqkvT, bqkvp, qkvp, 3 * DIM, DIM);

    attn_kernel<<<(BT * 16 * 2) / 8, 256>>>(qkvp, catp);

    // feedback projection: K=2048, fp32 out for LN2
    gemm_h<float, false><<<dim3(DIM / 128, BT / 256), 256, GSMEM_BYTES>>>(
        catp, wfbT, bfb, fbp, DIM, 2 * DIM);

    ln_kernel<<<BT, 256>>>(fbp, xp, g2, b2, nullptr, yhp);

    // output projection + GELU (fp32 out)
    gemm_h<float, true><<<dim3(DIM / 128, BT / 256), 256, GSMEM_BYTES>>>(
        yhp, woT, bo, out, DIM, DIM);
}

// round 7
// speedup vs baseline: 4.7154x; 1.0135x over previous
#include <cuda_runtime.h>
#include <cuda_fp16.h>
#include <math.h>
#include <stdint.h>

#define BT   8192
#define TT   4096
#define DIM  1024

// ---------------- scratch (device globals) ----------------
__device__ float  g_x  [BT * DIM];          // LN1 out fp32 (residual)
__device__ __half g_xh [BT * DIM];          // LN1 out fp16
__device__ __half g_qkv[BT * 3 * DIM];      // fused q|k|v
__device__ __half g_cat[BT * 2 * DIM];      // attn out (fwd|rev)
__device__ float  g_fb [BT * DIM];          // Wfb out fp32 (pre-LN2)
__device__ __half g_yh [BT * DIM];          // LN2 out fp16
__device__ __half g_wqkvT[3 * DIM * DIM];   // [3072][1024] = W^T fp16
__device__ __half g_wfbT [DIM * 2 * DIM];   // [1024][2048]
__device__ __half g_woT  [DIM * DIM];       // [1024][1024]
__device__ float  g_bqkv [3 * DIM];

// ---------------- helpers ----------------
__device__ __forceinline__ uint32_t smem_u32(const void* p) {
    uint32_t a;
    asm("{ .reg .u64 t; cvta.to.shared.u64 t, %1; cvt.u32.u64 %0, t; }" : "=r"(a) : "l"(p));
    return a;
}
__device__ __forceinline__ float gelu_exact(float x) {
    return 0.5f * x * (1.0f + erff(x * 0.7071067811865475f));
}
__device__ __forceinline__ float block_sum_256(float v, float* sh) {
    #pragma unroll
    for (int o = 16; o; o >>= 1) v += __shfl_xor_sync(0xffffffffu, v, o);
    int w = threadIdx.x >> 5;
    if ((threadIdx.x & 31) == 0) sh[w] = v;
    __syncthreads();
    if (threadIdx.x < 8) {
        float t = sh[threadIdx.x];
        #pragma unroll
        for (int o = 4; o; o >>= 1) t += __shfl_xor_sync(0xffu, t, o);
        if (threadIdx.x == 0) sh[0] = t;
    }
    __syncthreads();
    float r = sh[0];
    __syncthreads();
    return r;
}

__device__ __forceinline__ void mma_fp16(float* c, const uint32_t* a, const uint32_t* b) {
    asm volatile(
        "mma.sync.aligned.m16n8k16.row.col.f32.f16.f16.f32 "
        "{%0,%1,%2,%3}, {%4,%5,%6,%7}, {%8,%9}, {%0,%1,%2,%3};"
        : "+f"(c[0]), "+f"(c[1]), "+f"(c[2]), "+f"(c[3])
        : "r"(a[0]), "r"(a[1]), "r"(a[2]), "r"(a[3]), "r"(b[0]), "r"(b[1]));
}
#define LDSM4(r0, r1, r2, r3, addr) \
    asm volatile("ldmatrix.sync.aligned.m8n8.x4.shared.b16 {%0,%1,%2,%3}, [%4];" \
        : "=r"(r0), "=r"(r1), "=r"(r2), "=r"(r3) : "r"(addr))

#define CP16(dst, src) \
    asm volatile("cp.async.cg.shared.global [%0], [%1], 16;" :: "r"(dst), "l"(src))
#define CP_COMMIT() asm volatile("cp.async.commit_group;" ::: "memory")
#define CP_WAIT2()  asm volatile("cp.async.wait_group 2;" ::: "memory")

// ---------------- LayerNorm: fp32 in (+res) -> optional fp32 out + fp16 out ----------------
__global__ void ln_kernel(const float* __restrict__ in, const float* __restrict__ res,
                          const float* __restrict__ g, const float* __restrict__ b,
                          float* __restrict__ out32, __half* __restrict__ outh) {
    __shared__ float sh[8];
    int row = blockIdx.x;
    float4 v = ((const float4*)(in + (size_t)row * DIM))[threadIdx.x];
    if (res) {
        float4 r = ((const float4*)(res + (size_t)row * DIM))[threadIdx.x];
        v.x += r.x; v.y += r.y; v.z += r.z; v.w += r.w;
    }
    float s = block_sum_256(v.x + v.y + v.z + v.w, sh);
    float mean = s * (1.0f / DIM);
    float dx = v.x - mean, dy = v.y - mean, dz = v.z - mean, dw = v.w - mean;
    float sq = block_sum_256(dx*dx + dy*dy + dz*dz + dw*dw, sh);
    float scale = rsqrtf(sq * (1.0f / DIM) + 1e-6f);
    float4 gv = ((const float4*)g)[threadIdx.x];
    float4 bv = ((const float4*)b)[threadIdx.x];
    float4 o;
    o.x = dx * scale * gv.x + bv.x;
    o.y = dy * scale * gv.y + bv.y;
    o.z = dz * scale * gv.z + bv.z;
    o.w = dw * scale * gv.w + bv.w;
    if (out32) ((float4*)(out32 + (size_t)row * DIM))[threadIdx.x] = o;
    if (outh) {
        __half2* ph = (__half2*)(outh + (size_t)row * DIM);
        ph[2 * threadIdx.x + 0] = __floats2half2_rn(o.x, o.y);
        ph[2 * threadIdx.x + 1] = __floats2half2_rn(o.z, o.w);
    }
}

// ---------------- weight transpose+convert: W[R,C] fp32 -> WT[C,R] fp16 ----------------
__global__ void transpose_h(const float* __restrict__ W, __half* __restrict__ WT, int R, int C) {
    __shared__ float t[32][33];
    int c0 = blockIdx.x * 32, r0 = blockIdx.y * 32;
    int x = threadIdx.x, y = threadIdx.y;
    #pragma unroll
    for (int i = 0; i < 32; i += 8)
        t[y + i][x] = W[(size_t)(r0 + y + i) * C + c0 + x];
    __syncthreads();
    #pragma unroll
    for (int i = 0; i < 32; i += 8)
        WT[(size_t)(c0 + y + i) * R + r0 + x] = __float2half_rn(t[x][y + i]);
}

__global__ void concat_bias(const float* __restrict__ a, const float* __restrict__ b,
                            const float* __restrict__ c, float* __restrict__ o) {
    int i = blockIdx.x * blockDim.x + threadIdx.x;
    if (i < DIM) o[i] = a[i];
    else if (i < 2 * DIM) o[i] = b[i - DIM];
    else if (i < 3 * DIM) o[i] = c[i - 2 * DIM];
}

// ---------------- fp16 tensor-core GEMM (ldmatrix fragment path) ----------------
// C[M,N] = A[M,K] @ BT[N,K]^T + bias (+gelu).  256x128x32 tiles, 8 warps (4x2),
// 64x64 warp tiles, 4-stage cp.async ring, one __syncthreads per chunk.
#define ASH     40                       // smem row stride (halves); 80B → conflict-free ldmatrix
#define ASTAGE  (256 * ASH)              // halves
#define BSTAGE  (128 * ASH)
#define GSMEM_BYTES (4 * (ASTAGE + BSTAGE) * 2)   // 122880

template<typename OUT, bool GELU>
__global__ void __launch_bounds__(256, 1)
gemm_h(const __half* __restrict__ A, const __half* __restrict__ Bt,
       const float* __restrict__ bias, OUT* __restrict__ C, int N, int K) {
    extern __shared__ __align__(16) __half hsm[];
    __half* As = hsm;
    __half* Bs = hsm + 4 * ASTAGE;

    int tid = threadIdx.x;
    int wid = tid >> 5, lane = tid & 31;
    int wm = (wid >> 1) * 64;            // 4 m-warps
    int wn = (wid & 1) * 64;             // 2 n-warps
    int g = lane >> 2, t4 = lane & 3;
    int m0 = blockIdx.y << 8, n0 = blockIdx.x << 7;

    // ldmatrix lane->address maps
    int arow  = (lane & 7) | (((lane >> 3) & 1) << 3);   // 0..15
    int akoff = (lane >> 4) << 3;                        // 0 / 8 halves
    int brow  = (lane & 7) | ((lane >> 4) << 3);         // 0..15
    int bkoff = ((lane >> 3) & 1) << 3;
    uint32_t a_lane = smem_u32(As) + (uint32_t)(((wm + arow) * ASH + akoff) << 1);
    uint32_t b_lane = smem_u32(Bs) + (uint32_t)(((wn + brow) * ASH + bkoff) << 1);

    float acc[4][8][4];
    #pragma unroll
    for (int i = 0; i < 4; i++)
        #pragma unroll
        for (int j = 0; j < 8; j++)
            #pragma unroll
            for (int q = 0; q < 4; q++) acc[i][j][q] = 0.0f;

    auto cp_stage = [&](int s, int c) {
        const __half* Ab = A + (size_t)m0 * K + c * 32;
        #pragma unroll
        for (int j = 0; j < 4; j++) {
            int idx = tid + (j << 8);
            int ar = idx >> 2, ac = (idx & 3) << 3;
            CP16(smem_u32(As + s * ASTAGE + ar * ASH + ac), Ab + (size_t)ar * K + ac);
        }
        const __half* Bb = Bt + (size_t)n0 * K + c * 32;
        #pragma unroll
        for (int j = 0; j < 2; j++) {
            int idx = tid + (j << 8);
            int br = idx >> 2, bc = (idx & 3) << 3;
            CP16(smem_u32(Bs + s * BSTAGE + br * ASH + bc), Bb + (size_t)br * K + bc);
        }
        CP_COMMIT();
    };

    int NC = K >> 5;
    cp_stage(0, 0);
    cp_stage(1, 1);
    cp_stage(2, 2);

    for (int c = 0; c < NC; c++) {
        CP_WAIT2();
        __syncthreads();
        if (c + 3 < NC) cp_stage((c + 3) & 3, c + 3);
        else CP_COMMIT();                 // keep pending-group count exact

        int s = c & 3;
        uint32_t as_s = a_lane + (uint32_t)(s * ASTAGE * 2);
        uint32_t bs_s = b_lane + (uint32_t)(s * BSTAGE * 2);
        #pragma unroll
        for (int kk = 0; kk < 2; kk++) {
            uint32_t af[4][4], bf[8][2];
            #pragma unroll
            for (int mt = 0; mt < 4; mt++)
                LDSM4(af[mt][0], af[mt][1], af[mt][2], af[mt][3],
                      as_s + (uint32_t)(((mt * 16 * ASH) + kk * 16) << 1));
            #pragma unroll
            for (int np = 0; np < 4; np++)
                LDSM4(bf[2 * np][0], bf[2 * np][1], bf[2 * np + 1][0], bf[2 * np + 1][1],
                      bs_s + (uint32_t)(((np * 16 * ASH) + kk * 16) << 1));
            #pragma unroll
            for (int mt = 0; mt < 4; mt++)
                #pragma unroll
                for (int nt = 0; nt < 8; nt++)
                    mma_fp16(acc[mt][nt], af[mt], bf[nt]);
        }
    }

    // epilogue
    #pragma unroll
    for (int mt = 0; mt < 4; mt++) {
        int row = m0 + wm + mt * 16 + g;
        #pragma unroll
        for (int nt = 0; nt < 8; nt++) {
            int col = n0 + wn + nt * 8 + 2 * t4;
            float b0 = bias[col], b1 = bias[col + 1];
            float v00 = acc[mt][nt][0] + b0, v01 = acc[mt][nt][1] + b1;
            float v10 = acc[mt][nt][2] + b0, v11 = acc[mt][nt][3] + b1;
            if (GELU) {
                v00 = gelu_exact(v00); v01 = gelu_exact(v01);
                v10 = gelu_exact(v10); v11 = gelu_exact(v11);
            }
            if (sizeof(OUT) == 2) {
                *(__half2*)((__half*)C + (size_t)row * N + col) = __floats2half2_rn(v00, v01);
                *(__half2*)((__half*)C + (size_t)(row + 8) * N + col) = __floats2half2_rn(v10, v11);
            } else {
                *(float2*)((float*)C + (size_t)row * N + col) = make_float2(v00, v01);
                *(float2*)((float*)C + (size_t)(row + 8) * N + col) = make_float2(v10, v11);
            }
        }
    }
}

// ---------------- local windowed attention over fused qkv ----------------
__global__ void attn_kernel(const __half* __restrict__ qkv, __half* __restrict__ cat) {
    int warp = (blockIdx.x * blockDim.x + threadIdx.x) >> 5;
    int lane = threadIdx.x & 31;
    int dir = warp & 1;
    int h   = (warp >> 1) & 15;
    int tg  = warp >> 5;
    int b   = tg >> 12;
    int t   = tg & (TT - 1);
    int step = dir ? 1 : -1;
    int base = b << 12;
    int off  = h * 64 + lane * 2;

    int tq = t + step;
    float2 qv = make_float2(0.0f, 0.0f);
    if (tq >= 0 && tq < TT)
        qv = __half22float2(*(const __half2*)(qkv + (size_t)(base + tq) * 3072 + off));

    float s[3];
    float2 vv[3];
    #pragma unroll
    for (int j = 0; j < 3; j++) {
        int tk = t + step * j;
        float2 kv = make_float2(0.0f, 0.0f);
        float2 vj = make_float2(0.0f, 0.0f);
        if (tk >= 0 && tk < TT) {
            const __half* rp = qkv + (size_t)(base + tk) * 3072 + off;
            kv = __half22float2(*(const __half2*)(rp + DIM));
            vj = __half22float2(*(const __half2*)(rp + 2 * DIM));
        }
        float p = qv.x * kv.x + qv.y * kv.y;
        #pragma unroll
        for (int o = 16; o; o >>= 1) p += __shfl_xor_sync(0xffffffffu, p, o);
        s[j] = p * 0.125f;
        vv[j] = vj;
    }
    float m  = fmaxf(s[0], fmaxf(s[1], s[2]));
    float e0 = expf(s[0] - m), e1 = expf(s[1] - m), e2 = expf(s[2] - m);
    float inv = 1.0f / (e0 + e1 + e2);
    float ox = (e0 * vv[0].x + e1 * vv[1].x + e2 * vv[2].x) * inv;
    float oy = (e0 * vv[0].y + e1 * vv[1].y + e2 * vv[2].y) * inv;
    *(__half2*)(cat + (size_t)(base + t) * (2 * DIM) + dir * DIM + off) = __floats2half2_rn(ox, oy);
}

// ---------------- launch ----------------
extern "C" void kernel_launch(void* const* d_in, const int* in_sizes, int n_in,
                              void* d_out, int out_size) {
    const float* inp = (const float*)d_in[0];
    const float* Wq  = (const float*)d_in[1];
    const float* bq  = (const float*)d_in[2];
    const float* Wk  = (const float*)d_in[3];
    const float* bk  = (const float*)d_in[4];
    const float* Wv  = (const float*)d_in[5];
    const float* bv  = (const float*)d_in[6];
    const float* Wfb = (const float*)d_in[7];
    const float* bfb = (const float*)d_in[8];
    const float* Wo  = (const float*)d_in[9];
    const float* bo  = (const float*)d_in[10];
    const float* g1  = (const float*)d_in[11];
    const float* b1  = (const float*)d_in[12];
    const float* g2  = (const float*)d_in[13];
    const float* b2  = (const float*)d_in[14];
    float* out = (float*)d_out;

    float *xp, *fbp, *bqkvp;
    __half *xhp, *qkvp, *catp, *yhp, *wqkvT, *wfbT, *woT;
    cudaGetSymbolAddress((void**)&xp,    g_x);
    cudaGetSymbolAddress((void**)&xhp,   g_xh);
    cudaGetSymbolAddress((void**)&qkvp,  g_qkv);
    cudaGetSymbolAddress((void**)&catp,  g_cat);
    cudaGetSymbolAddress((void**)&fbp,   g_fb);
    cudaGetSymbolAddress((void**)&yhp,   g_yh);
    cudaGetSymbolAddress((void**)&wqkvT, g_wqkvT);
    cudaGetSymbolAddress((void**)&wfbT,  g_wfbT);
    cudaGetSymbolAddress((void**)&woT,   g_woT);
    cudaGetSymbolAddress((void**)&bqkvp, g_bqkv);

    cudaFuncSetAttribute(gemm_h<__half, false>, cudaFuncAttributeMaxDynamicSharedMemorySize, GSMEM_BYTES);
    cudaFuncSetAttribute(gemm_h<float, false>,  cudaFuncAttributeMaxDynamicSharedMemorySize, GSMEM_BYTES);
    cudaFuncSetAttribute(gemm_h<float, true>,   cudaFuncAttributeMaxDynamicSharedMemorySize, GSMEM_BYTES);

    dim3 tt(32, 8);
    transpose_h<<<dim3(32, 32), tt>>>(Wq,  wqkvT,                 DIM, DIM);
    transpose_h<<<dim3(32, 32), tt>>>(Wk,  wqkvT + DIM * DIM,     DIM, DIM);
    transpose_h<<<dim3(32, 32), tt>>>(Wv,  wqkvT + 2 * DIM * DIM, DIM, DIM);
    transpose_h<<<dim3(32, 64), tt>>>(Wfb, wfbT, 2 * DIM, DIM);
    transpose_h<<<dim3(32, 32), tt>>>(Wo,  woT,  DIM, DIM);
    concat_bias<<<12, 256>>>(bq, bk, bv, bqkvp);

    // LN1: fp32 residual + fp16 GEMM operand
    ln_kernel<<<BT, 256>>>(inp, nullptr, g1, b1, xp, xhp);

    // fused QKV projection: [8192,1024] @ [1024,3072]
    gemm_h<__half, false><<<dim3(3 * DIM / 128, BT / 256), 256, GSMEM_BYTES>>>(
        xhp, wqkvT, bqkvp, qkvp, 3 * DIM, DIM);

    attn_kernel<<<(BT * 16 * 2) / 8, 256>>>(qkvp, catp);

    // feedback projection: K=2048, fp32 out for LN2
    gemm_h<float, false><<<dim3(DIM / 128, BT / 256), 256, GSMEM_BYTES>>>(
        catp, wfbT, bfb, fbp, DIM, 2 * DIM);

    ln_kernel<<<BT, 256>>>(fbp, xp, g2, b2, nullptr, yhp);

    // output projection + GELU (fp32 out)
    gemm_h<float, true><<<dim3(DIM / 128, BT / 256), 256, GSMEM_BYTES>>>(
        yhp, woT, bo, out, DIM, DIM);
}

// round 8
// speedup vs baseline: 5.4921x; 1.1647x over previous
#include <cuda_runtime.h>
#include <cuda_fp16.h>
#include <math.h>
#include <stdint.h>

#define BT   8192
#define TT   4096
#define DIM  1024

// ---------------- scratch (device globals) ----------------
__device__ float  g_x  [BT * DIM];          // LN1 out fp32 (residual)
__device__ __half g_xh [BT * DIM];          // LN1 out fp16
__device__ __half g_qkv[BT * 3 * DIM];      // fused q|k|v
__device__ __half g_cat[BT * 2 * DIM];      // attn out (fwd|rev)
__device__ float  g_fb [BT * DIM];          // Wfb out fp32 (pre-LN2)
__device__ __half g_yh [BT * DIM];          // LN2 out fp16
__device__ __half g_wqkvT[3 * DIM * DIM];   // [3072][1024] = W^T fp16
__device__ __half g_wfbT [DIM * 2 * DIM];   // [1024][2048]
__device__ __half g_woT  [DIM * DIM];       // [1024][1024]
__device__ float  g_bqkv [3 * DIM];

// ---------------- helpers ----------------
__device__ __forceinline__ uint32_t smem_u32(const void* p) {
    uint32_t a;
    asm("{ .reg .u64 t; cvta.to.shared.u64 t, %1; cvt.u32.u64 %0, t; }" : "=r"(a) : "l"(p));
    return a;
}
__device__ __forceinline__ float gelu_exact(float x) {
    return 0.5f * x * (1.0f + erff(x * 0.7071067811865475f));
}
__device__ __forceinline__ float block_sum_256(float v, float* sh) {
    #pragma unroll
    for (int o = 16; o; o >>= 1) v += __shfl_xor_sync(0xffffffffu, v, o);
    int w = threadIdx.x >> 5;
    if ((threadIdx.x & 31) == 0) sh[w] = v;
    __syncthreads();
    if (threadIdx.x < 8) {
        float t = sh[threadIdx.x];
        #pragma unroll
        for (int o = 4; o; o >>= 1) t += __shfl_xor_sync(0xffu, t, o);
        if (threadIdx.x == 0) sh[0] = t;
    }
    __syncthreads();
    float r = sh[0];
    __syncthreads();
    return r;
}

__device__ __forceinline__ void mma_fp16(float* c, const uint32_t* a, const uint32_t* b) {
    asm volatile(
        "mma.sync.aligned.m16n8k16.row.col.f32.f16.f16.f32 "
        "{%0,%1,%2,%3}, {%4,%5,%6,%7}, {%8,%9}, {%0,%1,%2,%3};"
        : "+f"(c[0]), "+f"(c[1]), "+f"(c[2]), "+f"(c[3])
        : "r"(a[0]), "r"(a[1]), "r"(a[2]), "r"(a[3]), "r"(b[0]), "r"(b[1]));
}
#define LDSM4(r0, r1, r2, r3, addr) \
    asm volatile("ldmatrix.sync.aligned.m8n8.x4.shared.b16 {%0,%1,%2,%3}, [%4];" \
        : "=r"(r0), "=r"(r1), "=r"(r2), "=r"(r3) : "r"(addr))

#define CP16(dst, src) \
    asm volatile("cp.async.cg.shared.global [%0], [%1], 16;" :: "r"(dst), "l"(src))
#define CP_COMMIT() asm volatile("cp.async.commit_group;" ::: "memory")
#define CP_WAIT2()  asm volatile("cp.async.wait_group 2;" ::: "memory")

// ---------------- LayerNorm: fp32 in (+res) -> optional fp32 out + fp16 out ----------------
__global__ void ln_kernel(const float* __restrict__ in, const float* __restrict__ res,
                          const float* __restrict__ g, const float* __restrict__ b,
                          float* __restrict__ out32, __half* __restrict__ outh) {
    __shared__ float sh[8];
    int row = blockIdx.x;
    float4 v = ((const float4*)(in + (size_t)row * DIM))[threadIdx.x];
    if (res) {
        float4 r = ((const float4*)(res + (size_t)row * DIM))[threadIdx.x];
        v.x += r.x; v.y += r.y; v.z += r.z; v.w += r.w;
    }
    float s = block_sum_256(v.x + v.y + v.z + v.w, sh);
    float mean = s * (1.0f / DIM);
    float dx = v.x - mean, dy = v.y - mean, dz = v.z - mean, dw = v.w - mean;
    float sq = block_sum_256(dx*dx + dy*dy + dz*dz + dw*dw, sh);
    float scale = rsqrtf(sq * (1.0f / DIM) + 1e-6f);
    float4 gv = ((const float4*)g)[threadIdx.x];
    float4 bv = ((const float4*)b)[threadIdx.x];
    float4 o;
    o.x = dx * scale * gv.x + bv.x;
    o.y = dy * scale * gv.y + bv.y;
    o.z = dz * scale * gv.z + bv.z;
    o.w = dw * scale * gv.w + bv.w;
    if (out32) ((float4*)(out32 + (size_t)row * DIM))[threadIdx.x] = o;
    if (outh) {
        __half2* ph = (__half2*)(outh + (size_t)row * DIM);
        ph[2 * threadIdx.x + 0] = __floats2half2_rn(o.x, o.y);
        ph[2 * threadIdx.x + 1] = __floats2half2_rn(o.z, o.w);
    }
}

// ---------------- weight transpose+convert: W[R,C] fp32 -> WT[C,R] fp16 ----------------
__global__ void transpose_h(const float* __restrict__ W, __half* __restrict__ WT, int R, int C) {
    __shared__ float t[32][33];
    int c0 = blockIdx.x * 32, r0 = blockIdx.y * 32;
    int x = threadIdx.x, y = threadIdx.y;
    #pragma unroll
    for (int i = 0; i < 32; i += 8)
        t[y + i][x] = W[(size_t)(r0 + y + i) * C + c0 + x];
    __syncthreads();
    #pragma unroll
    for (int i = 0; i < 32; i += 8)
        WT[(size_t)(c0 + y + i) * R + r0 + x] = __float2half_rn(t[x][y + i]);
}

__global__ void concat_bias(const float* __restrict__ a, const float* __restrict__ b,
                            const float* __restrict__ c, float* __restrict__ o) {
    int i = blockIdx.x * blockDim.x + threadIdx.x;
    if (i < DIM) o[i] = a[i];
    else if (i < 2 * DIM) o[i] = b[i - DIM];
    else if (i < 3 * DIM) o[i] = c[i - 2 * DIM];
}

// ---------------- fp16 tensor-core GEMM (128x128 tiles, occupancy 2) ----------------
// C[M,N] = A[M,K] @ BT[N,K]^T + bias (+gelu).  128x128x32 tiles, 8 warps (4x2),
// 32x64 warp tiles, 4-stage cp.async ring, one __syncthreads per chunk.
#define ASH     40                       // smem row stride (halves); 80B → conflict-free ldmatrix
#define ASTAGE  (128 * ASH)              // halves
#define BSTAGE  (128 * ASH)
#define GSMEM_BYTES (4 * (ASTAGE + BSTAGE) * 2)   // 81920 → 2 CTAs/SM

template<typename OUT, bool GELU>
__global__ void __launch_bounds__(256, 2)
gemm_h(const __half* __restrict__ A, const __half* __restrict__ Bt,
       const float* __restrict__ bias, OUT* __restrict__ C, int N, int K) {
    extern __shared__ __align__(16) __half hsm[];
    __half* As = hsm;
    __half* Bs = hsm + 4 * ASTAGE;

    int tid = threadIdx.x;
    int wid = tid >> 5, lane = tid & 31;
    int wm = (wid >> 1) * 32;            // 4 m-warps
    int wn = (wid & 1) * 64;             // 2 n-warps
    int g = lane >> 2, t4 = lane & 3;
    int m0 = blockIdx.y << 7, n0 = blockIdx.x << 7;

    // ldmatrix lane->address maps
    int arow  = (lane & 7) | (((lane >> 3) & 1) << 3);   // 0..15
    int akoff = (lane >> 4) << 3;                        // 0 / 8 halves
    int brow  = (lane & 7) | ((lane >> 4) << 3);         // 0..15
    int bkoff = ((lane >> 3) & 1) << 3;
    uint32_t a_lane = smem_u32(As) + (uint32_t)(((wm + arow) * ASH + akoff) << 1);
    uint32_t b_lane = smem_u32(Bs) + (uint32_t)(((wn + brow) * ASH + bkoff) << 1);

    float acc[2][8][4];
    #pragma unroll
    for (int i = 0; i < 2; i++)
        #pragma unroll
        for (int j = 0; j < 8; j++)
            #pragma unroll
            for (int q = 0; q < 4; q++) acc[i][j][q] = 0.0f;

    auto cp_stage = [&](int s, int c) {
        const __half* Ab = A + (size_t)m0 * K + c * 32;
        #pragma unroll
        for (int j = 0; j < 2; j++) {
            int idx = tid + (j << 8);
            int ar = idx >> 2, ac = (idx & 3) << 3;
            CP16(smem_u32(As + s * ASTAGE + ar * ASH + ac), Ab + (size_t)ar * K + ac);
        }
        const __half* Bb = Bt + (size_t)n0 * K + c * 32;
        #pragma unroll
        for (int j = 0; j < 2; j++) {
            int idx = tid + (j << 8);
            int br = idx >> 2, bc = (idx & 3) << 3;
            CP16(smem_u32(Bs + s * BSTAGE + br * ASH + bc), Bb + (size_t)br * K + bc);
        }
        CP_COMMIT();
    };

    int NC = K >> 5;
    cp_stage(0, 0);
    cp_stage(1, 1);
    cp_stage(2, 2);

    for (int c = 0; c < NC; c++) {
        CP_WAIT2();
        __syncthreads();
        if (c + 3 < NC) cp_stage((c + 3) & 3, c + 3);
        else CP_COMMIT();                 // keep pending-group count exact

        int s = c & 3;
        uint32_t as_s = a_lane + (uint32_t)(s * ASTAGE * 2);
        uint32_t bs_s = b_lane + (uint32_t)(s * BSTAGE * 2);
        #pragma unroll
        for (int kk = 0; kk < 2; kk++) {
            uint32_t af[2][4], bf[8][2];
            #pragma unroll
            for (int mt = 0; mt < 2; mt++)
                LDSM4(af[mt][0], af[mt][1], af[mt][2], af[mt][3],
                      as_s + (uint32_t)(((mt * 16 * ASH) + kk * 16) << 1));
            #pragma unroll
            for (int np = 0; np < 4; np++)
                LDSM4(bf[2 * np][0], bf[2 * np][1], bf[2 * np + 1][0], bf[2 * np + 1][1],
                      bs_s + (uint32_t)(((np * 16 * ASH) + kk * 16) << 1));
            #pragma unroll
            for (int mt = 0; mt < 2; mt++)
                #pragma unroll
                for (int nt = 0; nt < 8; nt++)
                    mma_fp16(acc[mt][nt], af[mt], bf[nt]);
        }
    }

    // epilogue
    #pragma unroll
    for (int mt = 0; mt < 2; mt++) {
        int row = m0 + wm + mt * 16 + g;
        #pragma unroll
        for (int nt = 0; nt < 8; nt++) {
            int col = n0 + wn + nt * 8 + 2 * t4;
            float b0 = bias[col], b1 = bias[col + 1];
            float v00 = acc[mt][nt][0] + b0, v01 = acc[mt][nt][1] + b1;
            float v10 = acc[mt][nt][2] + b0, v11 = acc[mt][nt][3] + b1;
            if (GELU) {
                v00 = gelu_exact(v00); v01 = gelu_exact(v01);
                v10 = gelu_exact(v10); v11 = gelu_exact(v11);
            }
            if (sizeof(OUT) == 2) {
                *(__half2*)((__half*)C + (size_t)row * N + col) = __floats2half2_rn(v00, v01);
                *(__half2*)((__half*)C + (size_t)(row + 8) * N + col) = __floats2half2_rn(v10, v11);
            } else {
                *(float2*)((float*)C + (size_t)row * N + col) = make_float2(v00, v01);
                *(float2*)((float*)C + (size_t)(row + 8) * N + col) = make_float2(v10, v11);
            }
        }
    }
}

// ---------------- local windowed attention over fused qkv ----------------
__global__ void attn_kernel(const __half* __restrict__ qkv, __half* __restrict__ cat) {
    int warp = (blockIdx.x * blockDim.x + threadIdx.x) >> 5;
    int lane = threadIdx.x & 31;
    int dir = warp & 1;
    int h   = (warp >> 1) & 15;
    int tg  = warp >> 5;
    int b   = tg >> 12;
    int t   = tg & (TT - 1);
    int step = dir ? 1 : -1;
    int base = b << 12;
    int off  = h * 64 + lane * 2;

    int tq = t + step;
    float2 qv = make_float2(0.0f, 0.0f);
    if (tq >= 0 && tq < TT)
        qv = __half22float2(*(const __half2*)(qkv + (size_t)(base + tq) * 3072 + off));

    float s[3];
    float2 vv[3];
    #pragma unroll
    for (int j = 0; j < 3; j++) {
        int tk = t + step * j;
        float2 kv = make_float2(0.0f, 0.0f);
        float2 vj = make_float2(0.0f, 0.0f);
        if (tk >= 0 && tk < TT) {
            const __half* rp = qkv + (size_t)(base + tk) * 3072 + off;
            kv = __half22float2(*(const __half2*)(rp + DIM));
            vj = __half22float2(*(const __half2*)(rp + 2 * DIM));
        }
        float p = qv.x * kv.x + qv.y * kv.y;
        #pragma unroll
        for (int o = 16; o; o >>= 1) p += __shfl_xor_sync(0xffffffffu, p, o);
        s[j] = p * 0.125f;
        vv[j] = vj;
    }
    float m  = fmaxf(s[0], fmaxf(s[1], s[2]));
    float e0 = expf(s[0] - m), e1 = expf(s[1] - m), e2 = expf(s[2] - m);
    float inv = 1.0f / (e0 + e1 + e2);
    float ox = (e0 * vv[0].x + e1 * vv[1].x + e2 * vv[2].x) * inv;
    float oy = (e0 * vv[0].y + e1 * vv[1].y + e2 * vv[2].y) * inv;
    *(__half2*)(cat + (size_t)(base + t) * (2 * DIM) + dir * DIM + off) = __floats2half2_rn(ox, oy);
}

// ---------------- launch ----------------
extern "C" void kernel_launch(void* const* d_in, const int* in_sizes, int n_in,
                              void* d_out, int out_size) {
    const float* inp = (const float*)d_in[0];
    const float* Wq  = (const float*)d_in[1];
    const float* bq  = (const float*)d_in[2];
    const float* Wk  = (const float*)d_in[3];
    const float* bk  = (const float*)d_in[4];
    const float* Wv  = (const float*)d_in[5];
    const float* bv  = (const float*)d_in[6];
    const float* Wfb = (const float*)d_in[7];
    const float* bfb = (const float*)d_in[8];
    const float* Wo  = (const float*)d_in[9];
    const float* bo  = (const float*)d_in[10];
    const float* g1  = (const float*)d_in[11];
    const float* b1  = (const float*)d_in[12];
    const float* g2  = (const float*)d_in[13];
    const float* b2  = (const float*)d_in[14];
    float* out = (float*)d_out;

    float *xp, *fbp, *bqkvp;
    __half *xhp, *qkvp, *catp, *yhp, *wqkvT, *wfbT, *woT;
    cudaGetSymbolAddress((void**)&xp,    g_x);
    cudaGetSymbolAddress((void**)&xhp,   g_xh);
    cudaGetSymbolAddress((void**)&qkvp,  g_qkv);
    cudaGetSymbolAddress((void**)&catp,  g_cat);
    cudaGetSymbolAddress((void**)&fbp,   g_fb);
    cudaGetSymbolAddress((void**)&yhp,   g_yh);
    cudaGetSymbolAddress((void**)&wqkvT, g_wqkvT);
    cudaGetSymbolAddress((void**)&wfbT,  g_wfbT);
    cudaGetSymbolAddress((void**)&woT,   g_woT);
    cudaGetSymbolAddress((void**)&bqkvp, g_bqkv);

    cudaFuncSetAttribute(gemm_h<__half, false>, cudaFuncAttributeMaxDynamicSharedMemorySize, GSMEM_BYTES);
    cudaFuncSetAttribute(gemm_h<float, false>,  cudaFuncAttributeMaxDynamicSharedMemorySize, GSMEM_BYTES);
    cudaFuncSetAttribute(gemm_h<float, true>,   cudaFuncAttributeMaxDynamicSharedMemorySize, GSMEM_BYTES);

    dim3 tt(32, 8);
    transpose_h<<<dim3(32, 32), tt>>>(Wq,  wqkvT,                 DIM, DIM);
    transpose_h<<<dim3(32, 32), tt>>>(Wk,  wqkvT + DIM * DIM,     DIM, DIM);
    transpose_h<<<dim3(32, 32), tt>>>(Wv,  wqkvT + 2 * DIM * DIM, DIM, DIM);
    transpose_h<<<dim3(32, 64), tt>>>(Wfb, wfbT, 2 * DIM, DIM);
    transpose_h<<<dim3(32, 32), tt>>>(Wo,  woT,  DIM, DIM);
    concat_bias<<<12, 256>>>(bq, bk, bv, bqkvp);

    // LN1: fp32 residual + fp16 GEMM operand
    ln_kernel<<<BT, 256>>>(inp, nullptr, g1, b1, xp, xhp);

    // fused QKV projection: [8192,1024] @ [1024,3072]
    gemm_h<__half, false><<<dim3(3 * DIM / 128, BT / 128), 256, GSMEM_BYTES>>>(
        xhp, wqkvT, bqkvp, qkvp, 3 * DIM, DIM);

    attn_kernel<<<(BT * 16 * 2) / 8, 256>>>(qkvp, catp);

    // feedback projection: K=2048, fp32 out for LN2
    gemm_h<float, false><<<dim3(DIM / 128, BT / 128), 256, GSMEM_BYTES>>>(
        catp, wfbT, bfb, fbp, DIM, 2 * DIM);

    ln_kernel<<<BT, 256>>>(fbp, xp, g2, b2, nullptr, yhp);

    // output projection + GELU (fp32 out)
    gemm_h<float, true><<<dim3(DIM / 128, BT / 128), 256, GSMEM_BYTES>>>(
        yhp, woT, bo, out, DIM, DIM);
}

// round 10
// speedup vs baseline: 5.9712x; 1.0872x over previous
#include <cuda_runtime.h>
#include <cuda_fp16.h>
#include <math.h>
#include <stdint.h>

#define BT   8192
#define TT   4096
#define DIM  1024

// ---------------- scratch (device globals) ----------------
__device__ float  g_x  [BT * DIM];          // LN1 out fp32 (residual)
__device__ __half g_xh [BT * DIM];          // LN1 out fp16
__device__ __half g_qkv[BT * 3 * DIM];      // fused q|k|v
__device__ __half g_cat[BT * 2 * DIM];      // attn out (fwd|rev)
__device__ float  g_fb [BT * DIM];          // Wfb out fp32 (pre-LN2)
__device__ __half g_yh [BT * DIM];          // LN2 out fp16
__device__ __half g_wqkvT[3 * DIM * DIM];   // [3072][1024] = W^T fp16
__device__ __half g_wfbT [DIM * 2 * DIM];   // [1024][2048]
__device__ __half g_woT  [DIM * DIM];       // [1024][1024]
__device__ float  g_bqkv [3 * DIM];

// ---------------- helpers ----------------
__device__ __forceinline__ uint32_t smem_u32(const void* p) {
    uint32_t a;
    asm("{ .reg .u64 t; cvta.to.shared.u64 t, %1; cvt.u32.u64 %0, t; }" : "=r"(a) : "l"(p));
    return a;
}
__device__ __forceinline__ float gelu_exact(float x) {
    return 0.5f * x * (1.0f + erff(x * 0.7071067811865475f));
}
__device__ __forceinline__ float block_sum_256(float v, float* sh) {
    #pragma unroll
    for (int o = 16; o; o >>= 1) v += __shfl_xor_sync(0xffffffffu, v, o);
    int w = threadIdx.x >> 5;
    if ((threadIdx.x & 31) == 0) sh[w] = v;
    __syncthreads();
    if (threadIdx.x < 8) {
        float t = sh[threadIdx.x];
        #pragma unroll
        for (int o = 4; o; o >>= 1) t += __shfl_xor_sync(0xffu, t, o);
        if (threadIdx.x == 0) sh[0] = t;
    }
    __syncthreads();
    float r = sh[0];
    __syncthreads();
    return r;
}

__device__ __forceinline__ void mma_fp16(float* c, const uint32_t* a, const uint32_t* b) {
    asm volatile(
        "mma.sync.aligned.m16n8k16.row.col.f32.f16.f16.f32 "
        "{%0,%1,%2,%3}, {%4,%5,%6,%7}, {%8,%9}, {%0,%1,%2,%3};"
        : "+f"(c[0]), "+f"(c[1]), "+f"(c[2]), "+f"(c[3])
        : "r"(a[0]), "r"(a[1]), "r"(a[2]), "r"(a[3]), "r"(b[0]), "r"(b[1]));
}
#define LDSM4(r0, r1, r2, r3, addr) \
    asm volatile("ldmatrix.sync.aligned.m8n8.x4.shared.b16 {%0,%1,%2,%3}, [%4];" \
        : "=r"(r0), "=r"(r1), "=r"(r2), "=r"(r3) : "r"(addr))

#define CP16(dst, src) \
    asm volatile("cp.async.cg.shared.global [%0], [%1], 16;" :: "r"(dst), "l"(src))
#define CP_COMMIT() asm volatile("cp.async.commit_group;" ::: "memory")
#define CP_WAIT1()  asm volatile("cp.async.wait_group 1;" ::: "memory")

// ---------------- LayerNorm: fp32 in (+res) -> optional fp32 out + fp16 out ----------------
__global__ void ln_kernel(const float* __restrict__ in, const float* __restrict__ res,
                          const float* __restrict__ g, const float* __restrict__ b,
                          float* __restrict__ out32, __half* __restrict__ outh) {
    __shared__ float sh[8];
    int row = blockIdx.x;
    float4 v = ((const float4*)(in + (size_t)row * DIM))[threadIdx.x];
    if (res) {
        float4 r = ((const float4*)(res + (size_t)row * DIM))[threadIdx.x];
        v.x += r.x; v.y += r.y; v.z += r.z; v.w += r.w;
    }
    float s = block_sum_256(v.x + v.y + v.z + v.w, sh);
    float mean = s * (1.0f / DIM);
    float dx = v.x - mean, dy = v.y - mean, dz = v.z - mean, dw = v.w - mean;
    float sq = block_sum_256(dx*dx + dy*dy + dz*dz + dw*dw, sh);
    float scale = rsqrtf(sq * (1.0f / DIM) + 1e-6f);
    float4 gv = ((const float4*)g)[threadIdx.x];
    float4 bv = ((const float4*)b)[threadIdx.x];
    float4 o;
    o.x = dx * scale * gv.x + bv.x;
    o.y = dy * scale * gv.y + bv.y;
    o.z = dz * scale * gv.z + bv.z;
    o.w = dw * scale * gv.w + bv.w;
    if (out32) ((float4*)(out32 + (size_t)row * DIM))[threadIdx.x] = o;
    if (outh) {
        __half2* ph = (__half2*)(outh + (size_t)row * DIM);
        ph[2 * threadIdx.x + 0] = __floats2half2_rn(o.x, o.y);
        ph[2 * threadIdx.x + 1] = __floats2half2_rn(o.z, o.w);
    }
}

// ---------------- merged weight transpose+convert (5 weights, 1 launch) ----------------
__global__ void transpose_all(const float* __restrict__ Wq, const float* __restrict__ Wk,
                              const float* __restrict__ Wv, const float* __restrict__ Wfb,
                              const float* __restrict__ Wo,
                              __half* __restrict__ wqkvT, __half* __restrict__ wfbT,
                              __half* __restrict__ woT) {
    __shared__ float t[32][33];
    int by = blockIdx.y;
    const float* W;
    __half* WT;
    int R, rb;
    if (by < 32)       { W = Wq;  WT = wqkvT;               R = DIM;     rb = by; }
    else if (by < 64)  { W = Wk;  WT = wqkvT + DIM * DIM;   R = DIM;     rb = by - 32; }
    else if (by < 96)  { W = Wv;  WT = wqkvT + 2 * DIM * DIM; R = DIM;   rb = by - 64; }
    else if (by < 160) { W = Wfb; WT = wfbT;                R = 2 * DIM; rb = by - 96; }
    else               { W = Wo;  WT = woT;                 R = DIM;     rb = by - 160; }
    int c0 = blockIdx.x * 32, r0 = rb * 32;
    int x = threadIdx.x, y = threadIdx.y;
    #pragma unroll
    for (int i = 0; i < 32; i += 8)
        t[y + i][x] = W[(size_t)(r0 + y + i) * DIM + c0 + x];
    __syncthreads();
    #pragma unroll
    for (int i = 0; i < 32; i += 8)
        WT[(size_t)(c0 + y + i) * R + r0 + x] = __float2half_rn(t[x][y + i]);
}

__global__ void concat_bias(const float* __restrict__ a, const float* __restrict__ b,
                            const float* __restrict__ c, float* __restrict__ o) {
    int i = blockIdx.x * blockDim.x + threadIdx.x;
    if (i < DIM) o[i] = a[i];
    else if (i < 2 * DIM) o[i] = b[i - DIM];
    else if (i < 3 * DIM) o[i] = c[i - 2 * DIM];
}

// ---------------- fp16 tensor-core GEMM (128x128x64 chunks, occ 2) ----------------
// C[M,N] = A[M,K] @ BT[N,K]^T + bias (+gelu).  128x128 tiles, K-chunk 64,
// 8 warps (4x2), 32x64 warp tiles, 3-stage cp.async ring, 1 sync per chunk.
#define ASH     72                       // smem row stride (halves); 144B → conflict-free ldmatrix
#define ASTAGE  (128 * ASH)              // halves
#define BSTAGE  (128 * ASH)
#define GSMEM_BYTES (3 * (ASTAGE + BSTAGE) * 2)   // 110592 → 2 CTAs/SM

template<typename OUT, bool GELU>
__global__ void __launch_bounds__(256, 2)
gemm_h(const __half* __restrict__ A, const __half* __restrict__ Bt,
       const float* __restrict__ bias, OUT* __restrict__ C, int N, int K) {
    extern __shared__ __align__(16) __half hsm[];
    __half* As = hsm;
    __half* Bs = hsm + 3 * ASTAGE;

    int tid = threadIdx.x;
    int wid = tid >> 5, lane = tid & 31;
    int wm = (wid >> 1) * 32;            // 4 m-warps
    int wn = (wid & 1) * 64;             // 2 n-warps
    int g = lane >> 2, t4 = lane & 3;
    int m0 = blockIdx.y << 7, n0 = blockIdx.x << 7;

    // ldmatrix lane->address maps
    int arow  = (lane & 7) | (((lane >> 3) & 1) << 3);   // 0..15
    int akoff = (lane >> 4) << 3;                        // 0 / 8 halves
    int brow  = (lane & 7) | ((lane >> 4) << 3);         // 0..15
    int bkoff = ((lane >> 3) & 1) << 3;
    uint32_t a_lane = smem_u32(As) + (uint32_t)(((wm + arow) * ASH + akoff) << 1);
    uint32_t b_lane = smem_u32(Bs) + (uint32_t)(((wn + brow) * ASH + bkoff) << 1);

    float acc[2][8][4];
    #pragma unroll
    for (int i = 0; i < 2; i++)
        #pragma unroll
        for (int j = 0; j < 8; j++)
            #pragma unroll
            for (int q = 0; q < 4; q++) acc[i][j][q] = 0.0f;

    auto cp_stage = [&](int s, int c) {
        const __half* Ab = A + (size_t)m0 * K + c * 64;
        const __half* Bb = Bt + (size_t)n0 * K + c * 64;
        #pragma unroll
        for (int j = 0; j < 4; j++) {
            int idx = tid + (j << 8);
            int r = idx >> 3, cc = (idx & 7) << 3;
            CP16(smem_u32(As + s * ASTAGE + r * ASH + cc), Ab + (size_t)r * K + cc);
            CP16(smem_u32(Bs + s * BSTAGE + r * ASH + cc), Bb + (size_t)r * K + cc);
        }
        CP_COMMIT();
    };

    int NC = K >> 6;
    cp_stage(0, 0);
    cp_stage(1, 1);

    for (int c = 0; c < NC; c++) {
        CP_WAIT1();
        __syncthreads();
        if (c + 2 < NC) cp_stage((c + 2) % 3, c + 2);
        else CP_COMMIT();                 // keep pending-group count exact

        int s = c % 3;
        uint32_t as_s = a_lane + (uint32_t)(s * ASTAGE * 2);
        uint32_t bs_s = b_lane + (uint32_t)(s * BSTAGE * 2);
        #pragma unroll
        for (int kk = 0; kk < 4; kk++) {
            uint32_t af[2][4], bf[8][2];
            #pragma unroll
            for (int mt = 0; mt < 2; mt++)
                LDSM4(af[mt][0], af[mt][1], af[mt][2], af[mt][3],
                      as_s + (uint32_t)(((mt * 16 * ASH) + kk * 16) << 1));
            #pragma unroll
            for (int np = 0; np < 4; np++)
                LDSM4(bf[2 * np][0], bf[2 * np][1], bf[2 * np + 1][0], bf[2 * np + 1][1],
                      bs_s + (uint32_t)(((np * 16 * ASH) + kk * 16) << 1));
            #pragma unroll
            for (int mt = 0; mt < 2; mt++)
                #pragma unroll
                for (int nt = 0; nt < 8; nt++)
                    mma_fp16(acc[mt][nt], af[mt], bf[nt]);
        }
        __syncthreads();
    }

    // epilogue
    #pragma unroll
    for (int mt = 0; mt < 2; mt++) {
        int row = m0 + wm + mt * 16 + g;
        #pragma unroll
        for (int nt = 0; nt < 8; nt++) {
            int col = n0 + wn + nt * 8 + 2 * t4;
            float b0 = bias[col], b1 = bias[col + 1];
            float v00 = acc[mt][nt][0] + b0, v01 = acc[mt][nt][1] + b1;
            float v10 = acc[mt][nt][2] + b0, v11 = acc[mt][nt][3] + b1;
            if (GELU) {
                v00 = gelu_exact(v00); v01 = gelu_exact(v01);
                v10 = gelu_exact(v10); v11 = gelu_exact(v11);
            }
            if (sizeof(OUT) == 2) {
                *(__half2*)((__half*)C + (size_t)row * N + col) = __floats2half2_rn(v00, v01);
                *(__half2*)((__half*)C + (size_t)(row + 8) * N + col) = __floats2half2_rn(v10, v11);
            } else {
                *(float2*)((float*)C + (size_t)row * N + col) = make_float2(v00, v01);
                *(float2*)((float*)C + (size_t)(row + 8) * N + col) = make_float2(v10, v11);
            }
        }
    }
}

// ---------------- local windowed attention over fused qkv ----------------
__global__ void attn_kernel(const __half* __restrict__ qkv, __half* __restrict__ cat) {
    int warp = (blockIdx.x * blockDim.x + threadIdx.x) >> 5;
    int lane = threadIdx.x & 31;
    int dir = warp & 1;
    int h   = (warp >> 1) & 15;
    int tg  = warp >> 5;
    int b   = tg >> 12;
    int t   = tg & (TT - 1);
    int step = dir ? 1 : -1;
    int base = b << 12;
    int off  = h * 64 + lane * 2;

    int tq = t + step;
    float2 qv = make_float2(0.0f, 0.0f);
    if (tq >= 0 && tq < TT)
        qv = __half22float2(*(const __half2*)(qkv + (size_t)(base + tq) * 3072 + off));

    float s[3];
    float2 vv[3];
    #pragma unroll
    for (int j = 0; j < 3; j++) {
        int tk = t + step * j;
        float2 kv = make_float2(0.0f, 0.0f);
        float2 vj = make_float2(0.0f, 0.0f);
        if (tk >= 0 && tk < TT) {
            const __half* rp = qkv + (size_t)(base + tk) * 3072 + off;
            kv = __half22float2(*(const __half2*)(rp + DIM));
            vj = __half22float2(*(const __half2*)(rp + 2 * DIM));
        }
        float p = qv.x * kv.x + qv.y * kv.y;
        #pragma unroll
        for (int o = 16; o; o >>= 1) p += __shfl_xor_sync(0xffffffffu, p, o);
        s[j] = p * 0.125f;
        vv[j] = vj;
    }
    float m  = fmaxf(s[0], fmaxf(s[1], s[2]));
    float e0 = expf(s[0] - m), e1 = expf(s[1] - m), e2 = expf(s[2] - m);
    float inv = 1.0f / (e0 + e1 + e2);
    float ox = (e0 * vv[0].x + e1 * vv[1].x + e2 * vv[2].x) * inv;
    float oy = (e0 * vv[0].y + e1 * vv[1].y + e2 * vv[2].y) * inv;
    *(__half2*)(cat + (size_t)(base + t) * (2 * DIM) + dir * DIM + off) = __floats2half2_rn(ox, oy);
}

// ---------------- launch ----------------
extern "C" void kernel_launch(void* const* d_in, const int* in_sizes, int n_in,
                              void* d_out, int out_size) {
    const float* inp = (const float*)d_in[0];
    const float* Wq  = (const float*)d_in[1];
    const float* bq  = (const float*)d_in[2];
    const float* Wk  = (const float*)d_in[3];
    const float* bk  = (const float*)d_in[4];
    const float* Wv  = (const float*)d_in[5];
    const float* bv  = (const float*)d_in[6];
    const float* Wfb = (const float*)d_in[7];
    const float* bfb = (const float*)d_in[8];
    const float* Wo  = (const float*)d_in[9];
    const float* bo  = (const float*)d_in[10];
    const float* g1  = (const float*)d_in[11];
    const float* b1  = (const float*)d_in[12];
    const float* g2  = (const float*)d_in[13];
    const float* b2  = (const float*)d_in[14];
    float* out = (float*)d_out;

    float *xp, *fbp, *bqkvp;
    __half *xhp, *qkvp, *catp, *yhp, *wqkvT, *wfbT, *woT;
    cudaGetSymbolAddress((void**)&xp,    g_x);
    cudaGetSymbolAddress((void**)&xhp,   g_xh);
    cudaGetSymbolAddress((void**)&qkvp,  g_qkv);
    cudaGetSymbolAddress((void**)&catp,  g_cat);
    cudaGetSymbolAddress((void**)&fbp,   g_fb);
    cudaGetSymbolAddress((void**)&yhp,   g_yh);
    cudaGetSymbolAddress((void**)&wqkvT, g_wqkvT);
    cudaGetSymbolAddress((void**)&wfbT,  g_wfbT);
    cudaGetSymbolAddress((void**)&woT,   g_woT);
    cudaGetSymbolAddress((void**)&bqkvp, g_bqkv);

    cudaFuncSetAttribute(gemm_h<__half, false>, cudaFuncAttributeMaxDynamicSharedMemorySize, GSMEM_BYTES);
    cudaFuncSetAttribute(gemm_h<float, false>,  cudaFuncAttributeMaxDynamicSharedMemorySize, GSMEM_BYTES);
    cudaFuncSetAttribute(gemm_h<float, true>,   cudaFuncAttributeMaxDynamicSharedMemorySize, GSMEM_BYTES);

    transpose_all<<<dim3(32, 192), dim3(32, 8)>>>(Wq, Wk, Wv, Wfb, Wo, wqkvT, wfbT, woT);
    concat_bias<<<12, 256>>>(bq, bk, bv, bqkvp);

    // LN1: fp32 residual + fp16 GEMM operand
    ln_kernel<<<BT, 256>>>(inp, nullptr, g1, b1, xp, xhp);

    // fused QKV projection: [8192,1024] @ [1024,3072]
    gemm_h<__half, false><<<dim3(3 * DIM / 128, BT / 128), 256, GSMEM_BYTES>>>(
        xhp, wqkvT, bqkvp, qkvp, 3 * DIM, DIM);

    attn_kernel<<<(BT * 16 * 2) / 8, 256>>>(qkvp, catp);

    // feedback projection: K=2048, fp32 out for LN2
    gemm_h<float, false><<<dim3(DIM / 128, BT / 128), 256, GSMEM_BYTES>>>(
        catp, wfbT, bfb, fbp, DIM, 2 * DIM);

    ln_kernel<<<BT, 256>>>(fbp, xp, g2, b2, nullptr, yhp);

    // output projection + GELU (fp32 out)
    gemm_h<float, true><<<dim3(DIM / 128, BT / 128), 256, GSMEM_BYTES>>>(
        yhp, woT, bo, out, DIM, DIM);
}

// round 11
// speedup vs baseline: 5.9748x; 1.0006x over previous
#include <cuda_runtime.h>
#include <cuda_fp16.h>
#include <math.h>
#include <stdint.h>

#define BT   8192
#define TT   4096
#define DIM  1024

// ---------------- scratch (device globals) ----------------
__device__ float  g_x  [BT * DIM];          // LN1 out fp32 (residual)
__device__ __half g_xh [BT * DIM];          // LN1 out fp16
__device__ __half g_qkv[BT * 3 * DIM];      // fused q|k|v
__device__ __half g_cat[BT * 2 * DIM];      // attn out (fwd|rev)
__device__ float  g_fb [BT * DIM];          // Wfb out fp32 (pre-LN2)
__device__ __half g_yh [BT * DIM];          // LN2 out fp16
__device__ __half g_wqkvT[3 * DIM * DIM];   // [3072][1024] = W^T fp16
__device__ __half g_wfbT [DIM * 2 * DIM];   // [1024][2048]
__device__ __half g_woT  [DIM * DIM];       // [1024][1024]
__device__ float  g_bqkv [3 * DIM];

// ---------------- helpers ----------------
__device__ __forceinline__ uint32_t smem_u32(const void* p) {
    uint32_t a;
    asm("{ .reg .u64 t; cvta.to.shared.u64 t, %1; cvt.u32.u64 %0, t; }" : "=r"(a) : "l"(p));
    return a;
}
__device__ __forceinline__ float gelu_exact(float x) {
    return 0.5f * x * (1.0f + erff(x * 0.7071067811865475f));
}
__device__ __forceinline__ float block_sum_256(float v, float* sh) {
    #pragma unroll
    for (int o = 16; o; o >>= 1) v += __shfl_xor_sync(0xffffffffu, v, o);
    int w = threadIdx.x >> 5;
    if ((threadIdx.x & 31) == 0) sh[w] = v;
    __syncthreads();
    if (threadIdx.x < 8) {
        float t = sh[threadIdx.x];
        #pragma unroll
        for (int o = 4; o; o >>= 1) t += __shfl_xor_sync(0xffu, t, o);
        if (threadIdx.x == 0) sh[0] = t;
    }
    __syncthreads();
    float r = sh[0];
    __syncthreads();
    return r;
}

__device__ __forceinline__ void mma_fp16(float* c, const uint32_t* a, const uint32_t* b) {
    asm volatile(
        "mma.sync.aligned.m16n8k16.row.col.f32.f16.f16.f32 "
        "{%0,%1,%2,%3}, {%4,%5,%6,%7}, {%8,%9}, {%0,%1,%2,%3};"
        : "+f"(c[0]), "+f"(c[1]), "+f"(c[2]), "+f"(c[3])
        : "r"(a[0]), "r"(a[1]), "r"(a[2]), "r"(a[3]), "r"(b[0]), "r"(b[1]));
}
#define LDSM4(r0, r1, r2, r3, addr) \
    asm volatile("ldmatrix.sync.aligned.m8n8.x4.shared.b16 {%0,%1,%2,%3}, [%4];" \
        : "=r"(r0), "=r"(r1), "=r"(r2), "=r"(r3) : "r"(addr))

#define CP16(dst, src) \
    asm volatile("cp.async.cg.shared.global [%0], [%1], 16;" :: "r"(dst), "l"(src))
#define CP_COMMIT() asm volatile("cp.async.commit_group;" ::: "memory")
#define CP_WAIT1()  asm volatile("cp.async.wait_group 1;" ::: "memory")

// ---------------- LayerNorm: fp32 in (+res) -> optional fp32 out + fp16 out ----------------
__global__ void ln_kernel(const float* __restrict__ in, const float* __restrict__ res,
                          const float* __restrict__ g, const float* __restrict__ b,
                          float* __restrict__ out32, __half* __restrict__ outh) {
    __shared__ float sh[8];
    int row = blockIdx.x;
    float4 v = ((const float4*)(in + (size_t)row * DIM))[threadIdx.x];
    if (res) {
        float4 r = ((const float4*)(res + (size_t)row * DIM))[threadIdx.x];
        v.x += r.x; v.y += r.y; v.z += r.z; v.w += r.w;
    }
    float s = block_sum_256(v.x + v.y + v.z + v.w, sh);
    float mean = s * (1.0f / DIM);
    float dx = v.x - mean, dy = v.y - mean, dz = v.z - mean, dw = v.w - mean;
    float sq = block_sum_256(dx*dx + dy*dy + dz*dz + dw*dw, sh);
    float scale = rsqrtf(sq * (1.0f / DIM) + 1e-6f);
    float4 gv = ((const float4*)g)[threadIdx.x];
    float4 bv = ((const float4*)b)[threadIdx.x];
    float4 o;
    o.x = dx * scale * gv.x + bv.x;
    o.y = dy * scale * gv.y + bv.y;
    o.z = dz * scale * gv.z + bv.z;
    o.w = dw * scale * gv.w + bv.w;
    if (out32) ((float4*)(out32 + (size_t)row * DIM))[threadIdx.x] = o;
    if (outh) {
        __half2* ph = (__half2*)(outh + (size_t)row * DIM);
        ph[2 * threadIdx.x + 0] = __floats2half2_rn(o.x, o.y);
        ph[2 * threadIdx.x + 1] = __floats2half2_rn(o.z, o.w);
    }
}

// ---------------- merged weight transpose+convert (5 weights, 1 launch) ----------------
__global__ void transpose_all(const float* __restrict__ Wq, const float* __restrict__ Wk,
                              const float* __restrict__ Wv, const float* __restrict__ Wfb,
                              const float* __restrict__ Wo,
                              __half* __restrict__ wqkvT, __half* __restrict__ wfbT,
                              __half* __restrict__ woT) {
    __shared__ float t[32][33];
    int by = blockIdx.y;
    const float* W;
    __half* WT;
    int R, rb;
    if (by < 32)       { W = Wq;  WT = wqkvT;               R = DIM;     rb = by; }
    else if (by < 64)  { W = Wk;  WT = wqkvT + DIM * DIM;   R = DIM;     rb = by - 32; }
    else if (by < 96)  { W = Wv;  WT = wqkvT + 2 * DIM * DIM; R = DIM;   rb = by - 64; }
    else if (by < 160) { W = Wfb; WT = wfbT;                R = 2 * DIM; rb = by - 96; }
    else               { W = Wo;  WT = woT;                 R = DIM;     rb = by - 160; }
    int c0 = blockIdx.x * 32, r0 = rb * 32;
    int x = threadIdx.x, y = threadIdx.y;
    #pragma unroll
    for (int i = 0; i < 32; i += 8)
        t[y + i][x] = W[(size_t)(r0 + y + i) * DIM + c0 + x];
    __syncthreads();
    #pragma unroll
    for (int i = 0; i < 32; i += 8)
        WT[(size_t)(c0 + y + i) * R + r0 + x] = __float2half_rn(t[x][y + i]);
}

__global__ void concat_bias(const float* __restrict__ a, const float* __restrict__ b,
                            const float* __restrict__ c, float* __restrict__ o) {
    int i = blockIdx.x * blockDim.x + threadIdx.x;
    if (i < DIM) o[i] = a[i];
    else if (i < 2 * DIM) o[i] = b[i - DIM];
    else if (i < 3 * DIM) o[i] = c[i - 2 * DIM];
}

// ---------------- fp16 tensor-core GEMM (128x128x64, 4 warps, 64x64 warp tiles) ----------------
// C[M,N] = A[M,K] @ BT[N,K]^T + bias (+gelu).  128 threads, warp tile 64x64:
// per k16 step 8 LDSM.x4 feed 32 MMAs (2x FLOP/smem-byte vs 32x64 tiles).
// 3-stage cp.async ring, ONE __syncthreads per chunk.
#define ASH     72                       // smem row stride (halves); 144B → conflict-free ldmatrix
#define ASTAGE  (128 * ASH)              // halves
#define BSTAGE  (128 * ASH)
#define GSMEM_BYTES (3 * (ASTAGE + BSTAGE) * 2)   // 110592 → 2 CTAs/SM

template<typename OUT, bool GELU>
__global__ void __launch_bounds__(128, 2)
gemm_h(const __half* __restrict__ A, const __half* __restrict__ Bt,
       const float* __restrict__ bias, OUT* __restrict__ C, int N, int K) {
    extern __shared__ __align__(16) __half hsm[];
    __half* As = hsm;
    __half* Bs = hsm + 3 * ASTAGE;

    int tid = threadIdx.x;
    int wid = tid >> 5, lane = tid & 31;
    int wm = (wid >> 1) * 64;            // 2 m-warps
    int wn = (wid & 1) * 64;             // 2 n-warps
    int g = lane >> 2, t4 = lane & 3;
    int m0 = blockIdx.y << 7, n0 = blockIdx.x << 7;

    // ldmatrix lane->address maps
    int arow  = (lane & 7) | (((lane >> 3) & 1) << 3);   // 0..15
    int akoff = (lane >> 4) << 3;                        // 0 / 8 halves
    int brow  = (lane & 7) | ((lane >> 4) << 3);         // 0..15
    int bkoff = ((lane >> 3) & 1) << 3;
    uint32_t a_lane = smem_u32(As) + (uint32_t)(((wm + arow) * ASH + akoff) << 1);
    uint32_t b_lane = smem_u32(Bs) + (uint32_t)(((wn + brow) * ASH + bkoff) << 1);

    float acc[4][8][4];
    #pragma unroll
    for (int i = 0; i < 4; i++)
        #pragma unroll
        for (int j = 0; j < 8; j++)
            #pragma unroll
            for (int q = 0; q < 4; q++) acc[i][j][q] = 0.0f;

    auto cp_stage = [&](int s, int c) {
        const __half* Ab = A + (size_t)m0 * K + c * 64;
        const __half* Bb = Bt + (size_t)n0 * K + c * 64;
        #pragma unroll
        for (int j = 0; j < 8; j++) {
            int idx = tid + (j << 7);
            int r = idx >> 3, cc = (idx & 7) << 3;
            CP16(smem_u32(As + s * ASTAGE + r * ASH + cc), Ab + (size_t)r * K + cc);
            CP16(smem_u32(Bs + s * BSTAGE + r * ASH + cc), Bb + (size_t)r * K + cc);
        }
        CP_COMMIT();
    };

    int NC = K >> 6;
    cp_stage(0, 0);
    cp_stage(1, 1);

    for (int c = 0; c < NC; c++) {
        CP_WAIT1();
        __syncthreads();
        if (c + 2 < NC) cp_stage((c + 2) % 3, c + 2);
        else CP_COMMIT();                 // keep pending-group count exact

        int s = c % 3;
        uint32_t as_s = a_lane + (uint32_t)(s * ASTAGE * 2);
        uint32_t bs_s = b_lane + (uint32_t)(s * BSTAGE * 2);
        #pragma unroll
        for (int kk = 0; kk < 4; kk++) {
            uint32_t af[4][4], bf[8][2];
            #pragma unroll
            for (int mt = 0; mt < 4; mt++)
                LDSM4(af[mt][0], af[mt][1], af[mt][2], af[mt][3],
                      as_s + (uint32_t)(((mt * 16 * ASH) + kk * 16) << 1));
            #pragma unroll
            for (int np = 0; np < 4; np++)
                LDSM4(bf[2 * np][0], bf[2 * np][1], bf[2 * np + 1][0], bf[2 * np + 1][1],
                      bs_s + (uint32_t)(((np * 16 * ASH) + kk * 16) << 1));
            #pragma unroll
            for (int mt = 0; mt < 4; mt++)
                #pragma unroll
                for (int nt = 0; nt < 8; nt++)
                    mma_fp16(acc[mt][nt], af[mt], bf[nt]);
        }
        // NOTE: no loop-end sync. The chunk-start sync (post CP_WAIT1) already
        // guarantees all warps finished reading the stage that cp_stage will
        // overwrite (it was last read in chunk c-1, before everyone passed the
        // sync of chunk c).
    }

    // epilogue
    #pragma unroll
    for (int mt = 0; mt < 4; mt++) {
        int row = m0 + wm + mt * 16 + g;
        #pragma unroll
        for (int nt = 0; nt < 8; nt++) {
            int col = n0 + wn + nt * 8 + 2 * t4;
            float b0 = bias[col], b1 = bias[col + 1];
            float v00 = acc[mt][nt][0] + b0, v01 = acc[mt][nt][1] + b1;
            float v10 = acc[mt][nt][2] + b0, v11 = acc[mt][nt][3] + b1;
            if (GELU) {
                v00 = gelu_exact(v00); v01 = gelu_exact(v01);
                v10 = gelu_exact(v10); v11 = gelu_exact(v11);
            }
            if (sizeof(OUT) == 2) {
                *(__half2*)((__half*)C + (size_t)row * N + col) = __floats2half2_rn(v00, v01);
                *(__half2*)((__half*)C + (size_t)(row + 8) * N + col) = __floats2half2_rn(v10, v11);
            } else {
                *(float2*)((float*)C + (size_t)row * N + col) = make_float2(v00, v01);
                *(float2*)((float*)C + (size_t)(row + 8) * N + col) = make_float2(v10, v11);
            }
        }
    }
}

// ---------------- local windowed attention over fused qkv ----------------
__global__ void attn_kernel(const __half* __restrict__ qkv, __half* __restrict__ cat) {
    int warp = (blockIdx.x * blockDim.x + threadIdx.x) >> 5;
    int lane = threadIdx.x & 31;
    int dir = warp & 1;
    int h   = (warp >> 1) & 15;
    int tg  = warp >> 5;
    int b   = tg >> 12;
    int t   = tg & (TT - 1);
    int step = dir ? 1 : -1;
    int base = b << 12;
    int off  = h * 64 + lane * 2;

    int tq = t + step;
    float2 qv = make_float2(0.0f, 0.0f);
    if (tq >= 0 && tq < TT)
        qv = __half22float2(*(const __half2*)(qkv + (size_t)(base + tq) * 3072 + off));

    float s[3];
    float2 vv[3];
    #pragma unroll
    for (int j = 0; j < 3; j++) {
        int tk = t + step * j;
        float2 kv = make_float2(0.0f, 0.0f);
        float2 vj = make_float2(0.0f, 0.0f);
        if (tk >= 0 && tk < TT) {
            const __half* rp = qkv + (size_t)(base + tk) * 3072 + off;
            kv = __half22float2(*(const __half2*)(rp + DIM));
            vj = __half22float2(*(const __half2*)(rp + 2 * DIM));
        }
        float p = qv.x * kv.x + qv.y * kv.y;
        #pragma unroll
        for (int o = 16; o; o >>= 1) p += __shfl_xor_sync(0xffffffffu, p, o);
        s[j] = p * 0.125f;
        vv[j] = vj;
    }
    float m  = fmaxf(s[0], fmaxf(s[1], s[2]));
    float e0 = expf(s[0] - m), e1 = expf(s[1] - m), e2 = expf(s[2] - m);
    float inv = 1.0f / (e0 + e1 + e2);
    float ox = (e0 * vv[0].x + e1 * vv[1].x + e2 * vv[2].x) * inv;
    float oy = (e0 * vv[0].y + e1 * vv[1].y + e2 * vv[2].y) * inv;
    *(__half2*)(cat + (size_t)(base + t) * (2 * DIM) + dir * DIM + off) = __floats2half2_rn(ox, oy);
}

// ---------------- launch ----------------
extern "C" void kernel_launch(void* const* d_in, const int* in_sizes, int n_in,
                              void* d_out, int out_size) {
    const float* inp = (const float*)d_in[0];
    const float* Wq  = (const float*)d_in[1];
    const float* bq  = (const float*)d_in[2];
    const float* Wk  = (const float*)d_in[3];
    const float* bk  = (const float*)d_in[4];
    const float* Wv  = (const float*)d_in[5];
    const float* bv  = (const float*)d_in[6];
    const float* Wfb = (const float*)d_in[7];
    const float* bfb = (const float*)d_in[8];
    const float* Wo  = (const float*)d_in[9];
    const float* bo  = (const float*)d_in[10];
    const float* g1  = (const float*)d_in[11];
    const float* b1  = (const float*)d_in[12];
    const float* g2  = (const float*)d_in[13];
    const float* b2  = (const float*)d_in[14];
    float* out = (float*)d_out;

    float *xp, *fbp, *bqkvp;
    __half *xhp, *qkvp, *catp, *yhp, *wqkvT, *wfbT, *woT;
    cudaGetSymbolAddress((void**)&xp,    g_x);
    cudaGetSymbolAddress((void**)&xhp,   g_xh);
    cudaGetSymbolAddress((void**)&qkvp,  g_qkv);
    cudaGetSymbolAddress((void**)&catp,  g_cat);
    cudaGetSymbolAddress((void**)&fbp,   g_fb);
    cudaGetSymbolAddress((void**)&yhp,   g_yh);
    cudaGetSymbolAddress((void**)&wqkvT, g_wqkvT);
    cudaGetSymbolAddress((void**)&wfbT,  g_wfbT);
    cudaGetSymbolAddress((void**)&woT,   g_woT);
    cudaGetSymbolAddress((void**)&bqkvp, g_bqkv);

    cudaFuncSetAttribute(gemm_h<__half, false>, cudaFuncAttributeMaxDynamicSharedMemorySize, GSMEM_BYTES);
    cudaFuncSetAttribute(gemm_h<float, false>,  cudaFuncAttributeMaxDynamicSharedMemorySize, GSMEM_BYTES);
    cudaFuncSetAttribute(gemm_h<float, true>,   cudaFuncAttributeMaxDynamicSharedMemorySize, GSMEM_BYTES);

    transpose_all<<<dim3(32, 192), dim3(32, 8)>>>(Wq, Wk, Wv, Wfb, Wo, wqkvT, wfbT, woT);
    concat_bias<<<12, 256>>>(bq, bk, bv, bqkvp);

    // LN1: fp32 residual + fp16 GEMM operand
    ln_kernel<<<BT, 256>>>(inp, nullptr, g1, b1, xp, xhp);

    // fused QKV projection: [8192,1024] @ [1024,3072]
    gemm_h<__half, false><<<dim3(3 * DIM / 128, BT / 128), 128, GSMEM_BYTES>>>(
        xhp, wqkvT, bqkvp, qkvp, 3 * DIM, DIM);

    attn_kernel<<<(BT * 16 * 2) / 8, 256>>>(qkvp, catp);

    // feedback projection: K=2048, fp32 out for LN2
    gemm_h<float, false><<<dim3(DIM / 128, BT / 128), 128, GSMEM_BYTES>>>(
        catp, wfbT, bfb, fbp, DIM, 2 * DIM);

    ln_kernel<<<BT, 256>>>(fbp, xp, g2, b2, nullptr, yhp);

    // output projection + GELU (fp32 out)
    gemm_h<float, true><<<dim3(DIM / 128, BT / 128), 128, GSMEM_BYTES>>>(
        yhp, woT, bo, out, DIM, DIM);
}

// round 12
// speedup vs baseline: 6.1394x; 1.0276x over previous
#include <cuda_runtime.h>
#include <cuda_fp16.h>
#include <math.h>
#include <stdint.h>

#define BT   8192
#define TT   4096
#define DIM  1024

// ---------------- scratch (device globals) ----------------
__device__ float  g_x  [BT * DIM];          // LN1 out fp32 (residual)
__device__ __half g_xh [BT * DIM];          // LN1 out fp16
__device__ __half g_qkv[BT * 3 * DIM];      // fused q|k|v
__device__ __half g_cat[BT * 2 * DIM];      // attn out (fwd|rev)
__device__ __half g_fbh[BT * DIM];          // Wfb out fp16 (pre-LN2)
__device__ __half g_yh [BT * DIM];          // LN2 out fp16
__device__ __half g_wqkvT[3 * DIM * DIM];   // [3072][1024] = W^T fp16
__device__ __half g_wfbT [DIM * 2 * DIM];   // [1024][2048]
__device__ __half g_woT  [DIM * DIM];       // [1024][1024]
__device__ float  g_bqkv [3 * DIM];

// ---------------- helpers ----------------
__device__ __forceinline__ uint32_t smem_u32(const void* p) {
    uint32_t a;
    asm("{ .reg .u64 t; cvta.to.shared.u64 t, %1; cvt.u32.u64 %0, t; }" : "=r"(a) : "l"(p));
    return a;
}
__device__ __forceinline__ float gelu_exact(float x) {
    return 0.5f * x * (1.0f + erff(x * 0.7071067811865475f));
}
__device__ __forceinline__ float block_sum_256(float v, float* sh) {
    #pragma unroll
    for (int o = 16; o; o >>= 1) v += __shfl_xor_sync(0xffffffffu, v, o);
    int w = threadIdx.x >> 5;
    if ((threadIdx.x & 31) == 0) sh[w] = v;
    __syncthreads();
    if (threadIdx.x < 8) {
        float t = sh[threadIdx.x];
        #pragma unroll
        for (int o = 4; o; o >>= 1) t += __shfl_xor_sync(0xffu, t, o);
        if (threadIdx.x == 0) sh[0] = t;
    }
    __syncthreads();
    float r = sh[0];
    __syncthreads();
    return r;
}

__device__ __forceinline__ void mma_fp16(float* c, const uint32_t* a, const uint32_t* b) {
    asm volatile(
        "mma.sync.aligned.m16n8k16.row.col.f32.f16.f16.f32 "
        "{%0,%1,%2,%3}, {%4,%5,%6,%7}, {%8,%9}, {%0,%1,%2,%3};"
        : "+f"(c[0]), "+f"(c[1]), "+f"(c[2]), "+f"(c[3])
        : "r"(a[0]), "r"(a[1]), "r"(a[2]), "r"(a[3]), "r"(b[0]), "r"(b[1]));
}
#define LDSM4(r0, r1, r2, r3, addr) \
    asm volatile("ldmatrix.sync.aligned.m8n8.x4.shared.b16 {%0,%1,%2,%3}, [%4];" \
        : "=r"(r0), "=r"(r1), "=r"(r2), "=r"(r3) : "r"(addr))

#define CP16(dst, src) \
    asm volatile("cp.async.cg.shared.global [%0], [%1], 16;" :: "r"(dst), "l"(src))
#define CP_COMMIT() asm volatile("cp.async.commit_group;" ::: "memory")
#define CP_WAIT1()  asm volatile("cp.async.wait_group 1;" ::: "memory")

// ---------------- LayerNorm (templated input): IN (+fp32 res) -> opt fp32 + fp16 ----------------
template<typename IN>
__global__ void ln_kernel(const IN* __restrict__ in, const float* __restrict__ res,
                          const float* __restrict__ g, const float* __restrict__ b,
                          float* __restrict__ out32, __half* __restrict__ outh) {
    __shared__ float sh[8];
    int row = blockIdx.x;
    float4 v;
    if (sizeof(IN) == 2) {
        uint2 raw = ((const uint2*)((const __half*)in + (size_t)row * DIM))[threadIdx.x];
        float2 a = __half22float2(*(__half2*)&raw.x);
        float2 c = __half22float2(*(__half2*)&raw.y);
        v = make_float4(a.x, a.y, c.x, c.y);
    } else {
        v = ((const float4*)(const float*)in)[(size_t)row * (DIM / 4) + threadIdx.x];
    }
    if (res) {
        float4 r = ((const float4*)(res + (size_t)row * DIM))[threadIdx.x];
        v.x += r.x; v.y += r.y; v.z += r.z; v.w += r.w;
    }
    float s = block_sum_256(v.x + v.y + v.z + v.w, sh);
    float mean = s * (1.0f / DIM);
    float dx = v.x - mean, dy = v.y - mean, dz = v.z - mean, dw = v.w - mean;
    float sq = block_sum_256(dx*dx + dy*dy + dz*dz + dw*dw, sh);
    float scale = rsqrtf(sq * (1.0f / DIM) + 1e-6f);
    float4 gv = ((const float4*)g)[threadIdx.x];
    float4 bv = ((const float4*)b)[threadIdx.x];
    float4 o;
    o.x = dx * scale * gv.x + bv.x;
    o.y = dy * scale * gv.y + bv.y;
    o.z = dz * scale * gv.z + bv.z;
    o.w = dw * scale * gv.w + bv.w;
    if (out32) ((float4*)(out32 + (size_t)row * DIM))[threadIdx.x] = o;
    if (outh) {
        __half2* ph = (__half2*)(outh + (size_t)row * DIM);
        ph[2 * threadIdx.x + 0] = __floats2half2_rn(o.x, o.y);
        ph[2 * threadIdx.x + 1] = __floats2half2_rn(o.z, o.w);
    }
}

// ---------------- merged weight transpose+convert + bias concat (1 launch) ----------------
__global__ void transpose_all(const float* __restrict__ Wq, const float* __restrict__ Wk,
                              const float* __restrict__ Wv, const float* __restrict__ Wfb,
                              const float* __restrict__ Wo,
                              __half* __restrict__ wqkvT, __half* __restrict__ wfbT,
                              __half* __restrict__ woT,
                              const float* __restrict__ bq, const float* __restrict__ bk,
                              const float* __restrict__ bv, float* __restrict__ bqkv) {
    int by = blockIdx.y;
    if (by == 192) {                      // bias concat segment
        int i = blockIdx.x * 256 + threadIdx.y * 32 + threadIdx.x;
        if (i < DIM) bqkv[i] = bq[i];
        else if (i < 2 * DIM) bqkv[i] = bk[i - DIM];
        else if (i < 3 * DIM) bqkv[i] = bv[i - 2 * DIM];
        return;
    }
    __shared__ float t[32][33];
    const float* W;
    __half* WT;
    int R, rb;
    if (by < 32)       { W = Wq;  WT = wqkvT;                 R = DIM;     rb = by; }
    else if (by < 64)  { W = Wk;  WT = wqkvT + DIM * DIM;     R = DIM;     rb = by - 32; }
    else if (by < 96)  { W = Wv;  WT = wqkvT + 2 * DIM * DIM; R = DIM;     rb = by - 64; }
    else if (by < 160) { W = Wfb; WT = wfbT;                  R = 2 * DIM; rb = by - 96; }
    else               { W = Wo;  WT = woT;                   R = DIM;     rb = by - 160; }
    int c0 = blockIdx.x * 32, r0 = rb * 32;
    int x = threadIdx.x, y = threadIdx.y;
    #pragma unroll
    for (int i = 0; i < 32; i += 8)
        t[y + i][x] = W[(size_t)(r0 + y + i) * DIM + c0 + x];
    __syncthreads();
    #pragma unroll
    for (int i = 0; i < 32; i += 8)
        WT[(size_t)(c0 + y + i) * R + r0 + x] = __float2half_rn(t[x][y + i]);
}

// ---------------- fp16 tensor-core GEMM (unchanged from round 11) ----------------
#define ASH     72
#define ASTAGE  (128 * ASH)
#define BSTAGE  (128 * ASH)
#define GSMEM_BYTES (3 * (ASTAGE + BSTAGE) * 2)   // 110592 → 2 CTAs/SM

template<typename OUT, bool GELU>
__global__ void __launch_bounds__(128, 2)
gemm_h(const __half* __restrict__ A, const __half* __restrict__ Bt,
       const float* __restrict__ bias, OUT* __restrict__ C, int N, int K) {
    extern __shared__ __align__(16) __half hsm[];
    __half* As = hsm;
    __half* Bs = hsm + 3 * ASTAGE;

    int tid = threadIdx.x;
    int wid = tid >> 5, lane = tid & 31;
    int wm = (wid >> 1) * 64;
    int wn = (wid & 1) * 64;
    int g = lane >> 2, t4 = lane & 3;
    int m0 = blockIdx.y << 7, n0 = blockIdx.x << 7;

    int arow  = (lane & 7) | (((lane >> 3) & 1) << 3);
    int akoff = (lane >> 4) << 3;
    int brow  = (lane & 7) | ((lane >> 4) << 3);
    int bkoff = ((lane >> 3) & 1) << 3;
    uint32_t a_lane = smem_u32(As) + (uint32_t)(((wm + arow) * ASH + akoff) << 1);
    uint32_t b_lane = smem_u32(Bs) + (uint32_t)(((wn + brow) * ASH + bkoff) << 1);

    float acc[4][8][4];
    #pragma unroll
    for (int i = 0; i < 4; i++)
        #pragma unroll
        for (int j = 0; j < 8; j++)
            #pragma unroll
            for (int q = 0; q < 4; q++) acc[i][j][q] = 0.0f;

    auto cp_stage = [&](int s, int c) {
        const __half* Ab = A + (size_t)m0 * K + c * 64;
        const __half* Bb = Bt + (size_t)n0 * K + c * 64;
        #pragma unroll
        for (int j = 0; j < 8; j++) {
            int idx = tid + (j << 7);
            int r = idx >> 3, cc = (idx & 7) << 3;
            CP16(smem_u32(As + s * ASTAGE + r * ASH + cc), Ab + (size_t)r * K + cc);
            CP16(smem_u32(Bs + s * BSTAGE + r * ASH + cc), Bb + (size_t)r * K + cc);
        }
        CP_COMMIT();
    };

    int NC = K >> 6;
    cp_stage(0, 0);
    cp_stage(1, 1);

    for (int c = 0; c < NC; c++) {
        CP_WAIT1();
        __syncthreads();
        if (c + 2 < NC) cp_stage((c + 2) % 3, c + 2);
        else CP_COMMIT();

        int s = c % 3;
        uint32_t as_s = a_lane + (uint32_t)(s * ASTAGE * 2);
        uint32_t bs_s = b_lane + (uint32_t)(s * BSTAGE * 2);
        #pragma unroll
        for (int kk = 0; kk < 4; kk++) {
            uint32_t af[4][4], bf[8][2];
            #pragma unroll
            for (int mt = 0; mt < 4; mt++)
                LDSM4(af[mt][0], af[mt][1], af[mt][2], af[mt][3],
                      as_s + (uint32_t)(((mt * 16 * ASH) + kk * 16) << 1));
            #pragma unroll
            for (int np = 0; np < 4; np++)
                LDSM4(bf[2 * np][0], bf[2 * np][1], bf[2 * np + 1][0], bf[2 * np + 1][1],
                      bs_s + (uint32_t)(((np * 16 * ASH) + kk * 16) << 1));
            #pragma unroll
            for (int mt = 0; mt < 4; mt++)
                #pragma unroll
                for (int nt = 0; nt < 8; nt++)
                    mma_fp16(acc[mt][nt], af[mt], bf[nt]);
        }
    }

    #pragma unroll
    for (int mt = 0; mt < 4; mt++) {
        int row = m0 + wm + mt * 16 + g;
        #pragma unroll
        for (int nt = 0; nt < 8; nt++) {
            int col = n0 + wn + nt * 8 + 2 * t4;
            float b0 = bias[col], b1 = bias[col + 1];
            float v00 = acc[mt][nt][0] + b0, v01 = acc[mt][nt][1] + b1;
            float v10 = acc[mt][nt][2] + b0, v11 = acc[mt][nt][3] + b1;
            if (GELU) {
                v00 = gelu_exact(v00); v01 = gelu_exact(v01);
                v10 = gelu_exact(v10); v11 = gelu_exact(v11);
            }
            if (sizeof(OUT) == 2) {
                *(__half2*)((__half*)C + (size_t)row * N + col) = __floats2half2_rn(v00, v01);
                *(__half2*)((__half*)C + (size_t)(row + 8) * N + col) = __floats2half2_rn(v10, v11);
            } else {
                *(float2*)((float*)C + (size_t)row * N + col) = make_float2(v00, v01);
                *(float2*)((float*)C + (size_t)(row + 8) * N + col) = make_float2(v10, v11);
            }
        }
    }
}

// ---------------- local windowed attention: one warp = head-PAIR x dir, 8B lane loads ----------------
__global__ void attn_kernel(const __half* __restrict__ qkv, __half* __restrict__ cat) {
    int w = (blockIdx.x * blockDim.x + threadIdx.x) >> 5;
    int lane = threadIdx.x & 31;
    int dir = w & 1;
    int hp  = (w >> 1) & 7;          // head pair 0..7
    int tg  = w >> 4;
    int b   = tg >> 12;
    int t   = tg & (TT - 1);
    int step = dir ? 1 : -1;
    int base = b << 12;
    // lanes 0-15: head 2*hp, lanes 16-31: head 2*hp+1; 4 dims per lane
    int off = hp * 128 + (lane >> 4) * 64 + (lane & 15) * 4;

    int tq = t + step;
    float4 qv = make_float4(0.f, 0.f, 0.f, 0.f);
    if (tq >= 0 && tq < TT) {
        uint2 raw = *(const uint2*)(qkv + (size_t)(base + tq) * 3072 + off);
        float2 a = __half22float2(*(__half2*)&raw.x);
        float2 c = __half22float2(*(__half2*)&raw.y);
        qv = make_float4(a.x, a.y, c.x, c.y);
    }

    float s[3];
    float4 vv[3];
    #pragma unroll
    for (int j = 0; j < 3; j++) {
        int tk = t + step * j;
        float4 kv = make_float4(0.f, 0.f, 0.f, 0.f);
        float4 vj = make_float4(0.f, 0.f, 0.f, 0.f);
        if (tk >= 0 && tk < TT) {
            const __half* rp = qkv + (size_t)(base + tk) * 3072 + off;
            uint2 kraw = *(const uint2*)(rp + DIM);
            uint2 vraw = *(const uint2*)(rp + 2 * DIM);
            float2 k0 = __half22float2(*(__half2*)&kraw.x);
            float2 k1 = __half22float2(*(__half2*)&kraw.y);
            float2 v0 = __half22float2(*(__half2*)&vraw.x);
            float2 v1 = __half22float2(*(__half2*)&vraw.y);
            kv = make_float4(k0.x, k0.y, k1.x, k1.y);
            vj = make_float4(v0.x, v0.y, v1.x, v1.y);
        }
        float p = qv.x * kv.x + qv.y * kv.y + qv.z * kv.z + qv.w * kv.w;
        #pragma unroll
        for (int o = 8; o; o >>= 1) p += __shfl_xor_sync(0xffffffffu, p, o);
        s[j] = p * 0.125f;           // 1/sqrt(64)
        vv[j] = vj;
    }
    float m  = fmaxf(s[0], fmaxf(s[1], s[2]));
    float e0 = expf(s[0] - m), e1 = expf(s[1] - m), e2 = expf(s[2] - m);
    float inv = 1.0f / (e0 + e1 + e2);
    float o0 = (e0 * vv[0].x + e1 * vv[1].x + e2 * vv[2].x) * inv;
    float o1 = (e0 * vv[0].y + e1 * vv[1].y + e2 * vv[2].y) * inv;
    float o2 = (e0 * vv[0].z + e1 * vv[1].z + e2 * vv[2].z) * inv;
    float o3 = (e0 * vv[0].w + e1 * vv[1].w + e2 * vv[2].w) * inv;
    uint2 outp;
    *(__half2*)&outp.x = __floats2half2_rn(o0, o1);
    *(__half2*)&outp.y = __floats2half2_rn(o2, o3);
    *(uint2*)(cat + (size_t)(base + t) * (2 * DIM) + dir * DIM + off) = outp;
}

// ---------------- launch ----------------
extern "C" void kernel_launch(void* const* d_in, const int* in_sizes, int n_in,
                              void* d_out, int out_size) {
    const float* inp = (const float*)d_in[0];
    const float* Wq  = (const float*)d_in[1];
    const float* bq  = (const float*)d_in[2];
    const float* Wk  = (const float*)d_in[3];
    const float* bk  = (const float*)d_in[4];
    const float* Wv  = (const float*)d_in[5];
    const float* bv  = (const float*)d_in[6];
    const float* Wfb = (const float*)d_in[7];
    const float* bfb = (const float*)d_in[8];
    const float* Wo  = (const float*)d_in[9];
    const float* bo  = (const float*)d_in[10];
    const float* g1  = (const float*)d_in[11];
    const float* b1  = (const float*)d_in[12];
    const float* g2  = (const float*)d_in[13];
    const float* b2  = (const float*)d_in[14];
    float* out = (float*)d_out;

    float *xp, *bqkvp;
    __half *xhp, *qkvp, *catp, *fbhp, *yhp, *wqkvT, *wfbT, *woT;
    cudaGetSymbolAddress((void**)&xp,    g_x);
    cudaGetSymbolAddress((void**)&xhp,   g_xh);
    cudaGetSymbolAddress((void**)&qkvp,  g_qkv);
    cudaGetSymbolAddress((void**)&catp,  g_cat);
    cudaGetSymbolAddress((void**)&fbhp,  g_fbh);
    cudaGetSymbolAddress((void**)&yhp,   g_yh);
    cudaGetSymbolAddress((void**)&wqkvT, g_wqkvT);
    cudaGetSymbolAddress((void**)&wfbT,  g_wfbT);
    cudaGetSymbolAddress((void**)&woT,   g_woT);
    cudaGetSymbolAddress((void**)&bqkvp, g_bqkv);

    cudaFuncSetAttribute(gemm_h<__half, false>, cudaFuncAttributeMaxDynamicSharedMemorySize, GSMEM_BYTES);
    cudaFuncSetAttribute(gemm_h<float, true>,   cudaFuncAttributeMaxDynamicSharedMemorySize, GSMEM_BYTES);

    // weights transpose + bias concat (one launch)
    transpose_all<<<dim3(32, 193), dim3(32, 8)>>>(Wq, Wk, Wv, Wfb, Wo,
                                                  wqkvT, wfbT, woT, bq, bk, bv, bqkvp);

    // LN1: fp32 residual + fp16 GEMM operand
    ln_kernel<float><<<BT, 256>>>(inp, nullptr, g1, b1, xp, xhp);

    // fused QKV projection: [8192,1024] @ [1024,3072]
    gemm_h<__half, false><<<dim3(3 * DIM / 128, BT / 128), 128, GSMEM_BYTES>>>(
        xhp, wqkvT, bqkvp, qkvp, 3 * DIM, DIM);

    // attention: BT * 8 hpairs * 2 dirs warps, 8 warps/block
    attn_kernel<<<BT * 16 / 8, 256>>>(qkvp, catp);

    // feedback projection: K=2048, fp16 out
    gemm_h<__half, false><<<dim3(DIM / 128, BT / 128), 128, GSMEM_BYTES>>>(
        catp, wfbT, bfb, fbhp, DIM, 2 * DIM);

    // residual + LN2 (fp16 in + fp32 residual)
    ln_kernel<__half><<<BT, 256>>>(fbhp, xp, g2, b2, nullptr, yhp);

    // output projection + GELU (fp32 out)
    gemm_h<float, true><<<dim3(DIM / 128, BT / 128), 128, GSMEM_BYTES>>>(
        yhp, woT, bo, out, DIM, DIM);
}

// round 14
// speedup vs baseline: 6.2042x; 1.0105x over previous
#include <cuda_runtime.h>
#include <cuda_fp16.h>
#include <math.h>
#include <stdint.h>

#define BT   8192
#define TT   4096
#define DIM  1024

// ---------------- scratch (device globals) ----------------
__device__ float  g_x  [BT * DIM];          // LN1 out fp32 (residual)
__device__ __half g_xh [BT * DIM];          // LN1 out fp16
__device__ __half g_qkv[BT * 3 * DIM];      // fused q|k|v
__device__ __half g_cat[BT * 2 * DIM];      // attn out (fwd|rev)
__device__ __half g_fbh[BT * DIM];          // Wfb out fp16 (pre-LN2)
__device__ __half g_yh [BT * DIM];          // LN2 out fp16
__device__ __half g_wqkvT[3 * DIM * DIM];   // [3072][1024] = W^T fp16
__device__ __half g_wfbT [DIM * 2 * DIM];   // [1024][2048]
__device__ __half g_woT  [DIM * DIM];       // [1024][1024]
__device__ float  g_bqkv [3 * DIM];

// ---------------- helpers ----------------
__device__ __forceinline__ uint32_t smem_u32(const void* p) {
    uint32_t a;
    asm("{ .reg .u64 t; cvta.to.shared.u64 t, %1; cvt.u32.u64 %0, t; }" : "=r"(a) : "l"(p));
    return a;
}
__device__ __forceinline__ float gelu_exact(float x) {
    return 0.5f * x * (1.0f + erff(x * 0.7071067811865475f));
}
__device__ __forceinline__ float block_sum_256(float v, float* sh) {
    #pragma unroll
    for (int o = 16; o; o >>= 1) v += __shfl_xor_sync(0xffffffffu, v, o);
    int w = threadIdx.x >> 5;
    if ((threadIdx.x & 31) == 0) sh[w] = v;
    __syncthreads();
    if (threadIdx.x < 8) {
        float t = sh[threadIdx.x];
        #pragma unroll
        for (int o = 4; o; o >>= 1) t += __shfl_xor_sync(0xffu, t, o);
        if (threadIdx.x == 0) sh[0] = t;
    }
    __syncthreads();
    float r = sh[0];
    __syncthreads();
    return r;
}

__device__ __forceinline__ void mma_fp16(float* c, const uint32_t* a, const uint32_t* b) {
    asm volatile(
        "mma.sync.aligned.m16n8k16.row.col.f32.f16.f16.f32 "
        "{%0,%1,%2,%3}, {%4,%5,%6,%7}, {%8,%9}, {%0,%1,%2,%3};"
        : "+f"(c[0]), "+f"(c[1]), "+f"(c[2]), "+f"(c[3])
        : "r"(a[0]), "r"(a[1]), "r"(a[2]), "r"(a[3]), "r"(b[0]), "r"(b[1]));
}
#define LDSM4(r0, r1, r2, r3, addr) \
    asm volatile("ldmatrix.sync.aligned.m8n8.x4.shared.b16 {%0,%1,%2,%3}, [%4];" \
        : "=r"(r0), "=r"(r1), "=r"(r2), "=r"(r3) : "r"(addr))

#define CP16(dst, src) \
    asm volatile("cp.async.cg.shared.global [%0], [%1], 16;" :: "r"(dst), "l"(src))
#define CP_COMMIT() asm volatile("cp.async.commit_group;" ::: "memory")
#define CP_WAIT1()  asm volatile("cp.async.wait_group 1;" ::: "memory")

// ---------------- LayerNorm body (shared by prologue + ln_kernel) ----------------
template<typename IN>
__device__ __forceinline__ void ln_row(const IN* __restrict__ in, const float* __restrict__ res,
                                       const float* __restrict__ g, const float* __restrict__ b,
                                       float* __restrict__ out32, __half* __restrict__ outh,
                                       int row, float* sh) {
    float4 v;
    if (sizeof(IN) == 2) {
        uint2 raw = ((const uint2*)((const __half*)in + (size_t)row * DIM))[threadIdx.x];
        float2 a = __half22float2(*(__half2*)&raw.x);
        float2 c = __half22float2(*(__half2*)&raw.y);
        v = make_float4(a.x, a.y, c.x, c.y);
    } else {
        v = ((const float4*)(const float*)in)[(size_t)row * (DIM / 4) + threadIdx.x];
    }
    if (res) {
        float4 r = ((const float4*)(res + (size_t)row * DIM))[threadIdx.x];
        v.x += r.x; v.y += r.y; v.z += r.z; v.w += r.w;
    }
    float s = block_sum_256(v.x + v.y + v.z + v.w, sh);
    float mean = s * (1.0f / DIM);
    float dx = v.x - mean, dy = v.y - mean, dz = v.z - mean, dw = v.w - mean;
    float sq = block_sum_256(dx*dx + dy*dy + dz*dz + dw*dw, sh);
    float scale = rsqrtf(sq * (1.0f / DIM) + 1e-6f);
    float4 gv = ((const float4*)g)[threadIdx.x];
    float4 bv = ((const float4*)b)[threadIdx.x];
    float4 o;
    o.x = dx * scale * gv.x + bv.x;
    o.y = dy * scale * gv.y + bv.y;
    o.z = dz * scale * gv.z + bv.z;
    o.w = dw * scale * gv.w + bv.w;
    if (out32) ((float4*)(out32 + (size_t)row * DIM))[threadIdx.x] = o;
    if (outh) {
        __half2* ph = (__half2*)(outh + (size_t)row * DIM);
        ph[2 * threadIdx.x + 0] = __floats2half2_rn(o.x, o.y);
        ph[2 * threadIdx.x + 1] = __floats2half2_rn(o.z, o.w);
    }
}

template<typename IN>
__global__ void ln_kernel(const IN* __restrict__ in, const float* __restrict__ res,
                          const float* __restrict__ g, const float* __restrict__ b,
                          float* __restrict__ out32, __half* __restrict__ outh) {
    __shared__ float sh[8];
    ln_row<IN>(in, res, g, b, out32, outh, blockIdx.x, sh);
}

// ---------------- prologue: LN1 (blocks 0..BT-1) + weight transpose + bias concat ----------------
__global__ void prologue(const float* __restrict__ inp,
                         const float* __restrict__ Wq, const float* __restrict__ Wk,
                         const float* __restrict__ Wv, const float* __restrict__ Wfb,
                         const float* __restrict__ Wo,
                         __half* __restrict__ wqkvT, __half* __restrict__ wfbT,
                         __half* __restrict__ woT,
                         const float* __restrict__ bq, const float* __restrict__ bk,
                         const float* __restrict__ bv, float* __restrict__ bqkv,
                         const float* __restrict__ g1, const float* __restrict__ b1,
                         float* __restrict__ xp, __half* __restrict__ xhp) {
    __shared__ float sh[8];
    __shared__ float t[32][33];
    int bid = blockIdx.x;
    if (bid < BT) {                        // LN1 row
        ln_row<float>(inp, nullptr, g1, b1, xp, xhp, bid, sh);
        return;
    }
    int idx = bid - BT;
    int xblk = idx & 31;
    int seg  = idx >> 5;                   // 0..192
    int tid = threadIdx.x;
    if (seg == 192) {                      // bias concat
        int i = xblk * 256 + tid;
        if (i < DIM) bqkv[i] = bq[i];
        else if (i < 2 * DIM) bqkv[i] = bk[i - DIM];
        else if (i < 3 * DIM) bqkv[i] = bv[i - 2 * DIM];
        return;
    }
    const float* W;
    __half* WT;
    int R, rb;
    if (seg < 32)       { W = Wq;  WT = wqkvT;                 R = DIM;     rb = seg; }
    else if (seg < 64)  { W = Wk;  WT = wqkvT + DIM * DIM;     R = DIM;     rb = seg - 32; }
    else if (seg < 96)  { W = Wv;  WT = wqkvT + 2 * DIM * DIM; R = DIM;     rb = seg - 64; }
    else if (seg < 160) { W = Wfb; WT = wfbT;                  R = 2 * DIM; rb = seg - 96; }
    else                { W = Wo;  WT = woT;                   R = DIM;     rb = seg - 160; }
    int c0 = xblk * 32, r0 = rb * 32;
    int x = tid & 31, y = tid >> 5;        // 32x8 layout
    #pragma unroll
    for (int i = 0; i < 32; i += 8)
        t[y + i][x] = W[(size_t)(r0 + y + i) * DIM + c0 + x];
    __syncthreads();
    #pragma unroll
    for (int i = 0; i < 32; i += 8)
        WT[(size_t)(c0 + y + i) * R + r0 + x] = __float2half_rn(t[x][y + i]);
}

// ---------------- fp16 tensor-core GEMM (unchanged; at legacy-HMMA ceiling) ----------------
#define ASH     72
#define ASTAGE  (128 * ASH)
#define BSTAGE  (128 * ASH)
#define GSMEM_BYTES (3 * (ASTAGE + BSTAGE) * 2)   // 110592 → 2 CTAs/SM

template<typename OUT, bool GELU>
__global__ void __launch_bounds__(128, 2)
gemm_h(const __half* __restrict__ A, const __half* __restrict__ Bt,
       const float* __restrict__ bias, OUT* __restrict__ C, int N, int K) {
    extern __shared__ __align__(16) __half hsm[];
    __half* As = hsm;
    __half* Bs = hsm + 3 * ASTAGE;

    int tid = threadIdx.x;
    int wid = tid >> 5, lane = tid & 31;
    int wm = (wid >> 1) * 64;
    int wn = (wid & 1) * 64;
    int g = lane >> 2, t4 = lane & 3;
    int m0 = blockIdx.y << 7, n0 = blockIdx.x << 7;

    int arow  = (lane & 7) | (((lane >> 3) & 1) << 3);
    int akoff = (lane >> 4) << 3;
    int brow  = (lane & 7) | ((lane >> 4) << 3);
    int bkoff = ((lane >> 3) & 1) << 3;
    uint32_t a_lane = smem_u32(As) + (uint32_t)(((wm + arow) * ASH + akoff) << 1);
    uint32_t b_lane = smem_u32(Bs) + (uint32_t)(((wn + brow) * ASH + bkoff) << 1);

    float acc[4][8][4];
    #pragma unroll
    for (int i = 0; i < 4; i++)
        #pragma unroll
        for (int j = 0; j < 8; j++)
            #pragma unroll
            for (int q = 0; q < 4; q++) acc[i][j][q] = 0.0f;

    auto cp_stage = [&](int s, int c) {
        const __half* Ab = A + (size_t)m0 * K + c * 64;
        const __half* Bb = Bt + (size_t)n0 * K + c * 64;
        #pragma unroll
        for (int j = 0; j < 8; j++) {
            int idx = tid + (j << 7);
            int r = idx >> 3, cc = (idx & 7) << 3;
            CP16(smem_u32(As + s * ASTAGE + r * ASH + cc), Ab + (size_t)r * K + cc);
            CP16(smem_u32(Bs + s * BSTAGE + r * ASH + cc), Bb + (size_t)r * K + cc);
        }
        CP_COMMIT();
    };

    int NC = K >> 6;
    cp_stage(0, 0);
    cp_stage(1, 1);

    for (int c = 0; c < NC; c++) {
        CP_WAIT1();
        __syncthreads();
        if (c + 2 < NC) cp_stage((c + 2) % 3, c + 2);
        else CP_COMMIT();

        int s = c % 3;
        uint32_t as_s = a_lane + (uint32_t)(s * ASTAGE * 2);
        uint32_t bs_s = b_lane + (uint32_t)(s * BSTAGE * 2);
        #pragma unroll
        for (int kk = 0; kk < 4; kk++) {
            uint32_t af[4][4], bf[8][2];
            #pragma unroll
            for (int mt = 0; mt < 4; mt++)
                LDSM4(af[mt][0], af[mt][1], af[mt][2], af[mt][3],
                      as_s + (uint32_t)(((mt * 16 * ASH) + kk * 16) << 1));
            #pragma unroll
            for (int np = 0; np < 4; np++)
                LDSM4(bf[2 * np][0], bf[2 * np][1], bf[2 * np + 1][0], bf[2 * np + 1][1],
                      bs_s + (uint32_t)(((np * 16 * ASH) + kk * 16) << 1));
            #pragma unroll
            for (int mt = 0; mt < 4; mt++)
                #pragma unroll
                for (int nt = 0; nt < 8; nt++)
                    mma_fp16(acc[mt][nt], af[mt], bf[nt]);
        }
    }

    #pragma unroll
    for (int mt = 0; mt < 4; mt++) {
        int row = m0 + wm + mt * 16 + g;
        #pragma unroll
        for (int nt = 0; nt < 8; nt++) {
            int col = n0 + wn + nt * 8 + 2 * t4;
            float b0 = bias[col], b1 = bias[col + 1];
            float v00 = acc[mt][nt][0] + b0, v01 = acc[mt][nt][1] + b1;
            float v10 = acc[mt][nt][2] + b0, v11 = acc[mt][nt][3] + b1;
            if (GELU) {
                v00 = gelu_exact(v00); v01 = gelu_exact(v01);
                v10 = gelu_exact(v10); v11 = gelu_exact(v11);
            }
            if (sizeof(OUT) == 2) {
                *(__half2*)((__half*)C + (size_t)row * N + col) = __floats2half2_rn(v00, v01);
                *(__half2*)((__half*)C + (size_t)(row + 8) * N + col) = __floats2half2_rn(v10, v11);
            } else {
                *(float2*)((float*)C + (size_t)row * N + col) = make_float2(v00, v01);
                *(float2*)((float*)C + (size_t)(row + 8) * N + col) = make_float2(v10, v11);
            }
        }
    }
}

// ---------------- local windowed attention: issue-count diet ----------------
// One warp = head-pair x dir; fp32 scores, __expf softmax, half2 V weighted sum.
__global__ void attn_kernel(const __half* __restrict__ qkv, __half* __restrict__ cat) {
    int w = (blockIdx.x * blockDim.x + threadIdx.x) >> 5;
    int lane = threadIdx.x & 31;
    int dir = w & 1;
    int hp  = (w >> 1) & 7;
    int tg  = w >> 4;
    int b   = tg >> 12;
    int t   = tg & (TT - 1);
    int step = dir ? 1 : -1;
    int base = b << 12;
    int off = hp * 128 + (lane >> 4) * 64 + (lane & 15) * 4;

    int tq = t + step;
    float4 qv = make_float4(0.f, 0.f, 0.f, 0.f);
    if (tq >= 0 && tq < TT) {
        uint2 raw = *(const uint2*)(qkv + (size_t)(base + tq) * 3072 + off);
        float2 a = __half22float2(*(__half2*)&raw.x);
        float2 c = __half22float2(*(__half2*)&raw.y);
        qv = make_float4(a.x, a.y, c.x, c.y);
    }

    float s[3];
    uint2 vr[3];
    #pragma unroll
    for (int j = 0; j < 3; j++) {
        int tk = t + step * j;
        float4 kv = make_float4(0.f, 0.f, 0.f, 0.f);
        uint2 vraw = make_uint2(0u, 0u);
        if (tk >= 0 && tk < TT) {
            const __half* rp = qkv + (size_t)(base + tk) * 3072 + off;
            uint2 kraw = *(const uint2*)(rp + DIM);
            vraw = *(const uint2*)(rp + 2 * DIM);
            float2 k0 = __half22float2(*(__half2*)&kraw.x);
            float2 k1 = __half22float2(*(__half2*)&kraw.y);
            kv = make_float4(k0.x, k0.y, k1.x, k1.y);
        }
        float p = qv.x * kv.x + qv.y * kv.y + qv.z * kv.z + qv.w * kv.w;
        #pragma unroll
        for (int o = 8; o; o >>= 1) p += __shfl_xor_sync(0xffffffffu, p, o);
        s[j] = p * 0.125f;
        vr[j] = vraw;
    }
    float m  = fmaxf(s[0], fmaxf(s[1], s[2]));
    float e0 = __expf(s[0] - m), e1 = __expf(s[1] - m), e2 = __expf(s[2] - m);
    float inv = __fdividef(1.0f, e0 + e1 + e2);
    __half2 w0 = __float2half2_rn(e0 * inv);
    __half2 w1 = __float2half2_rn(e1 * inv);
    __half2 w2 = __float2half2_rn(e2 * inv);
    __half2 lo = __hmul2(w0, *(__half2*)&vr[0].x);
    lo = __hfma2(w1, *(__half2*)&vr[1].x, lo);
    lo = __hfma2(w2, *(__half2*)&vr[2].x, lo);
    __half2 hi = __hmul2(w0, *(__half2*)&vr[0].y);
    hi = __hfma2(w1, *(__half2*)&vr[1].y, hi);
    hi = __hfma2(w2, *(__half2*)&vr[2].y, hi);
    uint2 outp;
    *(__half2*)&outp.x = lo;
    *(__half2*)&outp.y = hi;
    *(uint2*)(cat + (size_t)(base + t) * (2 * DIM) + dir * DIM + off) = outp;
}

// ---------------- launch ----------------
extern "C" void kernel_launch(void* const* d_in, const int* in_sizes, int n_in,
                              void* d_out, int out_size) {
    const float* inp = (const float*)d_in[0];
    const float* Wq  = (const float*)d_in[1];
    const float* bq  = (const float*)d_in[2];
    const float* Wk  = (const float*)d_in[3];
    const float* bk  = (const float*)d_in[4];
    const float* Wv  = (const float*)d_in[5];
    const float* bv  = (const float*)d_in[6];
    const float* Wfb = (const float*)d_in[7];
    const float* bfb = (const float*)d_in[8];
    const float* Wo  = (const float*)d_in[9];
    const float* bo  = (const float*)d_in[10];
    const float* g1  = (const float*)d_in[11];
    const float* b1  = (const float*)d_in[12];
    const float* g2  = (const float*)d_in[13];
    const float* b2  = (const float*)d_in[14];
    float* out = (float*)d_out;

    float *xp, *bqkvp;
    __half *xhp, *qkvp, *catp, *fbhp, *yhp, *wqkvT, *wfbT, *woT;
    cudaGetSymbolAddress((void**)&xp,    g_x);
    cudaGetSymbolAddress((void**)&xhp,   g_xh);
    cudaGetSymbolAddress((void**)&qkvp,  g_qkv);
    cudaGetSymbolAddress((void**)&catp,  g_cat);
    cudaGetSymbolAddress((void**)&fbhp,  g_fbh);
    cudaGetSymbolAddress((void**)&yhp,   g_yh);
    cudaGetSymbolAddress((void**)&wqkvT, g_wqkvT);
    cudaGetSymbolAddress((void**)&wfbT,  g_wfbT);
    cudaGetSymbolAddress((void**)&woT,   g_woT);
    cudaGetSymbolAddress((void**)&bqkvp, g_bqkv);

    cudaFuncSetAttribute(gemm_h<__half, false>, cudaFuncAttributeMaxDynamicSharedMemorySize, GSMEM_BYTES);
    cudaFuncSetAttribute(gemm_h<float, true>,   cudaFuncAttributeMaxDynamicSharedMemorySize, GSMEM_BYTES);

    // LN1 + weight transpose + bias concat, one launch
    prologue<<<BT + 193 * 32, 256>>>(inp, Wq, Wk, Wv, Wfb, Wo,
                                     wqkvT, wfbT, woT, bq, bk, bv, bqkvp,
                                     g1, b1, xp, xhp);

    // fused QKV projection: [8192,1024] @ [1024,3072]
    gemm_h<__half, false><<<dim3(3 * DIM / 128, BT / 128), 128, GSMEM_BYTES>>>(
        xhp, wqkvT, bqkvp, qkvp, 3 * DIM, DIM);

    // attention
    attn_kernel<<<BT * 16 / 8, 256>>>(qkvp, catp);

    // feedback projection: K=2048, fp16 out
    gemm_h<__half, false><<<dim3(DIM / 128, BT / 128), 128, GSMEM_BYTES>>>(
        catp, wfbT, bfb, fbhp, DIM, 2 * DIM);

    // residual + LN2 (fp16 in + fp32 residual)
    ln_kernel<__half><<<BT, 256>>>(fbhp, xp, g2, b2, nullptr, yhp);

    // output projection + GELU (fp32 out)
    gemm_h<float, true><<<dim3(DIM / 128, BT / 128), 128, GSMEM_BYTES>>>(
        yhp, woT, bo, out, DIM, DIM);
}